// round 13
// baseline (speedup 1.0000x reference)
#include <cuda_runtime.h>
#include <cuda_fp16.h>
#include <cuda_bf16.h>
#include <cstdint>

#define N_NODES 50000
#define N_EDGES 800000
#define D       128
#define NL      3
#define BN_EPS  1e-5f
#define SCAN_NB 196   // ceil(50000/256)

// ---------------- scratch (no allocations allowed) ----------------
__device__ uint2  g_h[(size_t)N_NODES * 32];   // h rows, fp16 packed (4 cols / uint2)
__device__ float  g_agg[(size_t)N_NODES * D];
__device__ float  g_dinv[N_NODES];
__device__ int    g_degI[N_NODES];
__device__ int    g_colcnt[N_NODES];
__device__ int    g_offsets[N_NODES + 1];
__device__ int    g_cursor[N_NODES];
__device__ int    g_erow[N_EDGES];
__device__ int    g_blocksum[SCAN_NB];
__device__ float  g_stats[2 * D];
__device__ float  g_bn[2 * D];
__device__ int    g_is64;
// precomputed bf16 Markidis split of W for all layers
__device__ __nv_bfloat16 g_wh[NL * D * D];
__device__ __nv_bfloat16 g_wl[NL * D * D];

__device__ __forceinline__ uint32_t smem_u32(const void* p) {
    uint32_t a;
    asm("{ .reg .u64 t; cvta.to.shared.u64 t, %1; cvt.u32.u64 %0, t; }" : "=r"(a) : "l"(p));
    return a;
}
__device__ __forceinline__ void ldm_x4(uint32_t& r0, uint32_t& r1, uint32_t& r2,
                                       uint32_t& r3, uint32_t addr) {
    asm volatile("ldmatrix.sync.aligned.m8n8.x4.shared.b16 {%0,%1,%2,%3}, [%4];"
                 : "=r"(r0), "=r"(r1), "=r"(r2), "=r"(r3) : "r"(addr));
}
__device__ __forceinline__ void mma_bf16(float& d0, float& d1, float& d2, float& d3,
                                         uint32_t a0, uint32_t a1, uint32_t a2, uint32_t a3,
                                         uint32_t b0, uint32_t b1) {
    asm volatile("mma.sync.aligned.m16n8k16.row.col.f32.bf16.bf16.f32 "
                 "{%0,%1,%2,%3}, {%4,%5,%6,%7}, {%8,%9}, {%0,%1,%2,%3};"
                 : "+f"(d0), "+f"(d1), "+f"(d2), "+f"(d3)
                 : "r"(a0), "r"(a1), "r"(a2), "r"(a3), "r"(b0), "r"(b1));
}

// smem tiles: row-major [128][136] bf16 (272B stride -> conflict-free ldmatrix)
#define TPITCH 136
#define TILE_B (128 * TPITCH * 2)   // 34816 bytes
#define OFF_XH 0
#define OFF_XL (OFF_XH + TILE_B)
#define OFF_WH (OFF_XL + TILE_B)
#define OFF_WL (OFF_WH + TILE_B)
#define GEMM_SMEM (4 * TILE_B)      // 139264 bytes

// ---------------- preprocessing ----------------
__global__ void k_pre(const unsigned long long* __restrict__ ei) {
    for (int i = blockIdx.x * blockDim.x + threadIdx.x; i < N_NODES;
         i += gridDim.x * blockDim.x) {
        g_degI[i] = 0;
        g_colcnt[i] = 0;
    }
    if (blockIdx.x == 0 && threadIdx.x < 32) {
        unsigned long long v = ei[threadIdx.x];
        unsigned mask = __ballot_sync(0xffffffffu, (v >> 32) != 0ull);
        if (threadIdx.x == 0) g_is64 = (mask == 0u) ? 1 : 0;
    }
}

// one-shot: split all layers' W into bf16 hi/lo
__global__ void k_wsplit(const float* __restrict__ W) {
    int i = blockIdx.x * blockDim.x + threadIdx.x;
    if (i < NL * D * D) {
        float w = W[i];
        __nv_bfloat16 h = __float2bfloat16(w);
        g_wh[i] = h;
        g_wl[i] = __float2bfloat16(w - __bfloat162float(h));
    }
}

__device__ __forceinline__ void edge_rc(const void* ei, int is64, int e, int& r, int& c) {
    if (is64) {
        const long long* p = (const long long*)ei;
        r = (int)p[e];
        c = (int)p[N_EDGES + e];
    } else {
        const int* p = (const int*)ei;
        r = p[e];
        c = p[N_EDGES + e];
    }
}

// histogram, 2 edges per thread-iteration (vectorized reads)
__global__ void k_hist(const void* __restrict__ ei) {
    const int is64 = g_is64;
    const int half = N_EDGES / 2;   // 400000
    for (int e2 = blockIdx.x * blockDim.x + threadIdx.x; e2 < half;
         e2 += gridDim.x * blockDim.x) {
        int r0, r1, c0, c1;
        if (is64) {
            const longlong2* pr = (const longlong2*)ei;
            const longlong2* pc = pr + half;
            longlong2 rr = pr[e2];
            longlong2 cc = pc[e2];
            r0 = (int)rr.x; r1 = (int)rr.y;
            c0 = (int)cc.x; c1 = (int)cc.y;
        } else {
            const int2* pr = (const int2*)ei;
            const int2* pc = pr + half;
            int2 rr = pr[e2];
            int2 cc = pc[e2];
            r0 = rr.x; r1 = rr.y;
            c0 = cc.x; c1 = cc.y;
        }
        atomicAdd(&g_degI[r0], 1);
        atomicAdd(&g_degI[r1], 1);
        atomicAdd(&g_colcnt[c0], 1);
        atomicAdd(&g_colcnt[c1], 1);
    }
}

// ---- 3-stage multi-block exclusive scan of colcnt -> offsets (+cursor,+dinv) ----
__global__ void k_scan1() {
    __shared__ int wsum[8];
    const int tid = threadIdx.x, lane = tid & 31, wid = tid >> 5;
    int i = blockIdx.x * 256 + tid;
    int v = (i < N_NODES) ? g_colcnt[i] : 0;
    int x = v;
#pragma unroll
    for (int d = 1; d < 32; d <<= 1) {
        int t = __shfl_up_sync(0xffffffffu, x, d);
        if (lane >= d) x += t;
    }
    if (lane == 31) wsum[wid] = x;
    __syncthreads();
    if (wid == 0 && lane < 8) {
        int y = wsum[lane];
#pragma unroll
        for (int d = 1; d < 8; d <<= 1) {
            int t = __shfl_up_sync(0xffu, y, d);
            if (lane >= d) y += t;
        }
        wsum[lane] = y;
    }
    __syncthreads();
    int excl = x - v + (wid > 0 ? wsum[wid - 1] : 0);
    if (i < N_NODES) g_offsets[i] = excl;
    if (tid == 255) g_blocksum[blockIdx.x] = excl + v;
}

__global__ void k_scan2() {
    const int lane = threadIdx.x;
    int run = 0;
    for (int base = 0; base < SCAN_NB; base += 32) {
        int i = base + lane;
        int v = (i < SCAN_NB) ? g_blocksum[i] : 0;
        int x = v;
#pragma unroll
        for (int d = 1; d < 32; d <<= 1) {
            int t = __shfl_up_sync(0xffffffffu, x, d);
            if (lane >= d) x += t;
        }
        if (i < SCAN_NB) g_blocksum[i] = run + x - v;   // exclusive
        run += __shfl_sync(0xffffffffu, x, 31);
    }
}

__global__ void k_scan3() {
    int i = blockIdx.x * blockDim.x + threadIdx.x;
    if (i < N_NODES) {
        int o = g_offsets[i] + g_blocksum[i >> 8];
        g_offsets[i] = o;
        g_cursor[i] = o;
        int dg = g_degI[i];
        g_dinv[i] = (dg > 0) ? rsqrtf((float)dg) : 0.0f;
    }
    if (i == 0) g_offsets[N_NODES] = N_EDGES;
}

__global__ void k_fill(const void* __restrict__ ei) {
    int is64 = g_is64;
    for (int e = blockIdx.x * blockDim.x + threadIdx.x; e < N_EDGES;
         e += gridDim.x * blockDim.x) {
        int r, c;
        edge_rc(ei, is64, e, r, c);
        int p = atomicAdd(&g_cursor[c], 1);
        g_erow[p] = r;
    }
}

// ---------------- tensor GEMM: h = fp16((x@W^T + b)*dinv[row]) ----------------
// bf16 Markidis split: acc = xh*Wh + xh*Wl + xl*Wh (fp32 accum).
// CTA: 256 rows (two 128-row phases reusing smem-resident W), 512 threads / 16 warps.
__global__ void __launch_bounds__(512, 1)
k_gemm(const float* __restrict__ x, int layer, const float* __restrict__ bvec) {
    extern __shared__ char sm[];
    __nv_bfloat16* xh = (__nv_bfloat16*)(sm + OFF_XH);
    __nv_bfloat16* xl = (__nv_bfloat16*)(sm + OFF_XL);
    __nv_bfloat16* wh = (__nv_bfloat16*)(sm + OFF_WH);
    __nv_bfloat16* wl = (__nv_bfloat16*)(sm + OFF_WL);

    const int tid = threadIdx.x, lane = tid & 31, wid = tid >> 5;

    // copy precomputed W splits once per CTA (bf16, no math)
    {
        const uint4* gwh = (const uint4*)(g_wh + layer * D * D);
        const uint4* gwl = (const uint4*)(g_wl + layer * D * D);
        for (int t = tid; t < 2048; t += 512) {
            int r = t >> 4, c8 = (t & 15) * 8;
            *(uint4*)&wh[r * TPITCH + c8] = gwh[t];
            *(uint4*)&wl[r * TPITCH + c8] = gwl[t];
        }
    }
    if (blockIdx.x == 0 && tid < 2 * D) g_stats[tid] = 0.0f;

    const int wm = wid >> 2;          // 0..3 : rows wm*32 .. +31
    const int wn = wid & 3;           // 0..3 : cols wn*32 .. +31
    const int lrow = lane & 15;
    const int lksh = (lane >> 4) * 8;
    const uint32_t sxh = smem_u32(xh), sxl = smem_u32(xl);
    const uint32_t swh = smem_u32(wh), swl = smem_u32(wl);
    const int g = lane >> 2, tg = lane & 3;
    uint32_t* hw = (uint32_t*)g_h;

#pragma unroll
    for (int phase = 0; phase < 2; phase++) {
        const int row0 = blockIdx.x * 256 + phase * 128;
        if (row0 >= N_NODES) break;
        if (phase) __syncthreads();   // prior MMA reads of xh/xl done

        // load + split x tile
        for (int t = tid; t < 4096; t += 512) {
            int r = t >> 5, c = (t & 31) * 4;
            int gr = row0 + r;
            float4 v = (gr < N_NODES) ? *(const float4*)&x[(size_t)gr * D + c]
                                      : make_float4(0.f, 0.f, 0.f, 0.f);
            __nv_bfloat16 h0 = __float2bfloat16(v.x), h1 = __float2bfloat16(v.y);
            __nv_bfloat16 h2 = __float2bfloat16(v.z), h3 = __float2bfloat16(v.w);
            __nv_bfloat162 hp0 = __halves2bfloat162(h0, h1), hp1 = __halves2bfloat162(h2, h3);
            __nv_bfloat162 lp0 = __halves2bfloat162(__float2bfloat16(v.x - __bfloat162float(h0)),
                                                    __float2bfloat16(v.y - __bfloat162float(h1)));
            __nv_bfloat162 lp1 = __halves2bfloat162(__float2bfloat16(v.z - __bfloat162float(h2)),
                                                    __float2bfloat16(v.w - __bfloat162float(h3)));
            uint2 ph, pl;
            ph.x = *(unsigned*)&hp0; ph.y = *(unsigned*)&hp1;
            pl.x = *(unsigned*)&lp0; pl.y = *(unsigned*)&lp1;
            *(uint2*)&xh[r * TPITCH + c] = ph;
            *(uint2*)&xl[r * TPITCH + c] = pl;
        }
        __syncthreads();

        float acc[2][4][4];
#pragma unroll
        for (int mi = 0; mi < 2; mi++)
#pragma unroll
            for (int ni = 0; ni < 4; ni++)
#pragma unroll
                for (int j = 0; j < 4; j++) acc[mi][ni][j] = 0.0f;

#pragma unroll
        for (int pass = 0; pass < 3; pass++) {
            const uint32_t abase = (pass == 2) ? sxl : sxh;
            const uint32_t bbase = (pass == 1) ? swl : swh;
#pragma unroll
            for (int k0 = 0; k0 < 128; k0 += 16) {
                uint32_t af[2][4];
#pragma unroll
                for (int mi = 0; mi < 2; mi++) {
                    uint32_t a = abase +
                        (uint32_t)(((wm * 32 + mi * 16 + lrow) * TPITCH + k0 + lksh) * 2);
                    ldm_x4(af[mi][0], af[mi][1], af[mi][2], af[mi][3], a);
                }
                uint32_t bf[2][4];
#pragma unroll
                for (int nh = 0; nh < 2; nh++) {
                    uint32_t a = bbase +
                        (uint32_t)(((wn * 32 + nh * 16 + lrow) * TPITCH + k0 + lksh) * 2);
                    ldm_x4(bf[nh][0], bf[nh][1], bf[nh][2], bf[nh][3], a);
                }
#pragma unroll
                for (int mi = 0; mi < 2; mi++)
#pragma unroll
                    for (int ni = 0; ni < 4; ni++) {
                        int nh = ni >> 1, nl = ni & 1;
                        mma_bf16(acc[mi][ni][0], acc[mi][ni][1], acc[mi][ni][2], acc[mi][ni][3],
                                 af[mi][0], af[mi][1], af[mi][2], af[mi][3],
                                 bf[nh][nl], bf[nh][nl + 2]);
                    }
            }
        }

        // epilogue: (acc + bias) * dinv[row] -> fp16 pairs
#pragma unroll
        for (int mi = 0; mi < 2; mi++) {
            int r0g = row0 + wm * 32 + mi * 16 + g;
            int r1g = r0g + 8;
            float dv0 = (r0g < N_NODES) ? g_dinv[r0g] : 0.0f;
            float dv1 = (r1g < N_NODES) ? g_dinv[r1g] : 0.0f;
#pragma unroll
            for (int ni = 0; ni < 4; ni++) {
                int c = wn * 32 + ni * 8 + 2 * tg;
                float b0 = bvec[c], b1 = bvec[c + 1];
                if (r0g < N_NODES) {
                    __half2 p = __floats2half2_rn((acc[mi][ni][0] + b0) * dv0,
                                                  (acc[mi][ni][1] + b1) * dv0);
                    hw[(size_t)r0g * 64 + (c >> 1)] = *(uint32_t*)&p;
                }
                if (r1g < N_NODES) {
                    __half2 p = __floats2half2_rn((acc[mi][ni][2] + b0) * dv1,
                                                  (acc[mi][ni][3] + b1) * dv1);
                    hw[(size_t)r1g * 64 + (c >> 1)] = *(uint32_t*)&p;
                }
            }
        }
    }
}

// ---------------- gather: agg[n] = dinv[n] * sum_{e: col=n} h[row_e]; fused BN stats ----------------
// (R8-proven structure: 32 lanes per row, uint2 loads, one edge per iteration)
__global__ void k_gather() {
    const int lane = threadIdx.x & 31;
    const int warp = threadIdx.x >> 5;
    const int gw   = blockIdx.x * 8 + warp;
    const int nw   = gridDim.x * 8;
    const uint2* __restrict__ hp = g_h;
    float4* ap = (float4*)g_agg;

    float s0 = 0.f, s1 = 0.f, s2 = 0.f, s3 = 0.f;
    float q0 = 0.f, q1 = 0.f, q2 = 0.f, q3 = 0.f;

    for (int node = gw; node < N_NODES; node += nw) {
        int st = g_offsets[node];
        int en = g_offsets[node + 1];
        float4 acc = make_float4(0.f, 0.f, 0.f, 0.f);
        for (int i = st; i < en; i += 32) {
            int idx = 0;
            if (i + lane < en) idx = g_erow[i + lane];
            int n = min(32, en - i);
#pragma unroll 4
            for (int j = 0; j < n; j++) {
                int r = __shfl_sync(0xffffffffu, idx, j);
                uint2 v = hp[(size_t)r * 32 + lane];
                __half2 a = *reinterpret_cast<__half2*>(&v.x);
                __half2 b = *reinterpret_cast<__half2*>(&v.y);
                float2 f0 = __half22float2(a);
                float2 f1 = __half22float2(b);
                acc.x += f0.x; acc.y += f0.y; acc.z += f1.x; acc.w += f1.y;
            }
        }
        float dc = g_dinv[node];
        acc.x *= dc; acc.y *= dc; acc.z *= dc; acc.w *= dc;
        ap[node * 32 + lane] = acc;
        s0 += acc.x; s1 += acc.y; s2 += acc.z; s3 += acc.w;
        q0 += acc.x * acc.x; q1 += acc.y * acc.y;
        q2 += acc.z * acc.z; q3 += acc.w * acc.w;
    }

    __shared__ float ssum[128], ssq[128];
    if (threadIdx.x < 128) { ssum[threadIdx.x] = 0.f; ssq[threadIdx.x] = 0.f; }
    __syncthreads();
    int c = lane * 4;
    atomicAdd(&ssum[c + 0], s0); atomicAdd(&ssum[c + 1], s1);
    atomicAdd(&ssum[c + 2], s2); atomicAdd(&ssum[c + 3], s3);
    atomicAdd(&ssq[c + 0], q0); atomicAdd(&ssq[c + 1], q1);
    atomicAdd(&ssq[c + 2], q2); atomicAdd(&ssq[c + 3], q3);
    __syncthreads();
    if (threadIdx.x < 128) {
        atomicAdd(&g_stats[threadIdx.x], ssum[threadIdx.x]);
        atomicAdd(&g_stats[D + threadIdx.x], ssq[threadIdx.x]);
    }
}

__global__ void k_bnfinal(const float* __restrict__ gamma, const float* __restrict__ beta) {
    int c = threadIdx.x;
    const float inv_n = 1.0f / (float)N_NODES;
    float mu  = g_stats[c] * inv_n;
    float var = g_stats[D + c] * inv_n - mu * mu;
    float sc  = gamma[c] * rsqrtf(var + BN_EPS);
    g_bn[c]     = sc;
    g_bn[D + c] = beta[c] - mu * sc;
}

__global__ void k_apply(const float* __restrict__ xsrc, float* __restrict__ xdst) {
    int i = blockIdx.x * blockDim.x + threadIdx.x;
    if (i >= N_NODES * 32) return;
    int cq = i & 31;
    float4 a  = ((const float4*)g_agg)[i];
    float4 xv = ((const float4*)xsrc)[i];
    float4 sc = ((const float4*)g_bn)[cq];
    float4 sh = ((const float4*)(g_bn + D))[cq];
    float4 o;
    o.x = xv.x + fmaxf(fmaf(a.x, sc.x, sh.x), 0.f);
    o.y = xv.y + fmaxf(fmaf(a.y, sc.y, sh.y), 0.f);
    o.z = xv.z + fmaxf(fmaf(a.z, sc.z, sh.z), 0.f);
    o.w = xv.w + fmaxf(fmaf(a.w, sc.w, sh.w), 0.f);
    ((float4*)xdst)[i] = o;
}

// ---------------- launch ----------------
extern "C" void kernel_launch(void* const* d_in, const int* in_sizes, int n_in,
                              void* d_out, int out_size) {
    const float* x     = (const float*)d_in[0];
    const void*  ei    = d_in[1];
    const float* W     = (const float*)d_in[2];
    const float* bvec  = (const float*)d_in[3];
    const float* gamma = (const float*)d_in[4];
    const float* beta  = (const float*)d_in[5];
    float* out = (float*)d_out;

    cudaFuncSetAttribute(k_gemm, cudaFuncAttributeMaxDynamicSharedMemorySize, GEMM_SMEM);

    k_pre<<<160, 256>>>((const unsigned long long*)ei);      // 0
    k_wsplit<<<(NL * D * D + 511) / 512, 512>>>(W);          // 1
    k_hist<<<1024, 256>>>(ei);                               // 2
    k_scan1<<<SCAN_NB, 256>>>();                             // 3
    k_scan2<<<1, 32>>>();                                    // 4
    k_scan3<<<(N_NODES + 255) / 256, 256>>>();               // 5

    const float* xin = x;
    const int gemm_blocks  = (N_NODES + 255) / 256;          // 196
    const int apply_blocks = (N_NODES * 32 + 255) / 256;

    for (int l = 0; l < NL; l++) {
        k_gemm<<<gemm_blocks, 512, GEMM_SMEM>>>(xin, l, bvec + l * D);
        if (l == 0) k_fill<<<1024, 256>>>(ei);
        k_gather<<<1024, 256>>>();
        k_bnfinal<<<1, 128>>>(gamma + l * D, beta + l * D);
        k_apply<<<apply_blocks, 256>>>(xin, out);
        xin = out;
    }
}

// round 14
// speedup vs baseline: 1.1022x; 1.1022x over previous
#include <cuda_runtime.h>
#include <cuda_fp16.h>
#include <cuda_bf16.h>
#include <cstdint>

#define N_NODES 50000
#define N_EDGES 800000
#define D       128
#define NL      3
#define BN_EPS  1e-5f
#define SCAN_NB 196   // ceil(50000/256)

// ---------------- scratch (no allocations allowed) ----------------
__device__ uint2  g_h[(size_t)N_NODES * 32];   // h rows, fp16 packed (4 cols / uint2)
__device__ float  g_agg[(size_t)N_NODES * D];
__device__ float  g_dinv[N_NODES];
__device__ int    g_degI[N_NODES];
__device__ int    g_colcnt[N_NODES];
__device__ int    g_offsets[N_NODES + 1];
__device__ int    g_cursor[N_NODES];
__device__ int    g_erow[N_EDGES];
__device__ int    g_blocksum[SCAN_NB];
__device__ float  g_stats[2 * D];
__device__ float  g_bn[2 * D];
__device__ int    g_is64;
// precomputed bf16 Markidis split of W for all layers
__device__ __nv_bfloat16 g_wh[NL * D * D];
__device__ __nv_bfloat16 g_wl[NL * D * D];

__device__ __forceinline__ uint32_t smem_u32(const void* p) {
    uint32_t a;
    asm("{ .reg .u64 t; cvta.to.shared.u64 t, %1; cvt.u32.u64 %0, t; }" : "=r"(a) : "l"(p));
    return a;
}
__device__ __forceinline__ void ldm_x4(uint32_t& r0, uint32_t& r1, uint32_t& r2,
                                       uint32_t& r3, uint32_t addr) {
    asm volatile("ldmatrix.sync.aligned.m8n8.x4.shared.b16 {%0,%1,%2,%3}, [%4];"
                 : "=r"(r0), "=r"(r1), "=r"(r2), "=r"(r3) : "r"(addr));
}
__device__ __forceinline__ void mma_bf16(float& d0, float& d1, float& d2, float& d3,
                                         uint32_t a0, uint32_t a1, uint32_t a2, uint32_t a3,
                                         uint32_t b0, uint32_t b1) {
    asm volatile("mma.sync.aligned.m16n8k16.row.col.f32.bf16.bf16.f32 "
                 "{%0,%1,%2,%3}, {%4,%5,%6,%7}, {%8,%9}, {%0,%1,%2,%3};"
                 : "+f"(d0), "+f"(d1), "+f"(d2), "+f"(d3)
                 : "r"(a0), "r"(a1), "r"(a2), "r"(a3), "r"(b0), "r"(b1));
}

// smem tiles: row-major [128][136] bf16 (272B stride -> conflict-free ldmatrix)
#define TPITCH 136
#define TILE_B (128 * TPITCH * 2)   // 34816 bytes
#define OFF_XH 0
#define OFF_XL (OFF_XH + TILE_B)
#define OFF_WH (OFF_XL + TILE_B)
#define OFF_WL (OFF_WH + TILE_B)
#define GEMM_SMEM (4 * TILE_B)      // 139264 bytes

// ---------------- preprocessing ----------------
__global__ void k_pre(const unsigned long long* __restrict__ ei) {
    for (int i = blockIdx.x * blockDim.x + threadIdx.x; i < N_NODES;
         i += gridDim.x * blockDim.x) {
        g_degI[i] = 0;
        g_colcnt[i] = 0;
    }
    if (blockIdx.x == 0 && threadIdx.x < 32) {
        unsigned long long v = ei[threadIdx.x];
        unsigned mask = __ballot_sync(0xffffffffu, (v >> 32) != 0ull);
        if (threadIdx.x == 0) g_is64 = (mask == 0u) ? 1 : 0;
    }
}

// one-shot: split all layers' W into bf16 hi/lo
__global__ void k_wsplit(const float* __restrict__ W) {
    int i = blockIdx.x * blockDim.x + threadIdx.x;
    if (i < NL * D * D) {
        float w = W[i];
        __nv_bfloat16 h = __float2bfloat16(w);
        g_wh[i] = h;
        g_wl[i] = __float2bfloat16(w - __bfloat162float(h));
    }
}

__device__ __forceinline__ void edge_rc(const void* ei, int is64, int e, int& r, int& c) {
    if (is64) {
        const long long* p = (const long long*)ei;
        r = (int)p[e];
        c = (int)p[N_EDGES + e];
    } else {
        const int* p = (const int*)ei;
        r = p[e];
        c = p[N_EDGES + e];
    }
}

__global__ void k_hist(const void* __restrict__ ei) {
    int is64 = g_is64;
    for (int e = blockIdx.x * blockDim.x + threadIdx.x; e < N_EDGES;
         e += gridDim.x * blockDim.x) {
        int r, c;
        edge_rc(ei, is64, e, r, c);
        atomicAdd(&g_degI[r], 1);
        atomicAdd(&g_colcnt[c], 1);
    }
}

// ---- 3-stage multi-block exclusive scan of colcnt -> offsets (+cursor,+dinv) ----
__global__ void k_scan1() {
    __shared__ int wsum[8];
    const int tid = threadIdx.x, lane = tid & 31, wid = tid >> 5;
    int i = blockIdx.x * 256 + tid;
    int v = (i < N_NODES) ? g_colcnt[i] : 0;
    int x = v;
#pragma unroll
    for (int d = 1; d < 32; d <<= 1) {
        int t = __shfl_up_sync(0xffffffffu, x, d);
        if (lane >= d) x += t;
    }
    if (lane == 31) wsum[wid] = x;
    __syncthreads();
    if (wid == 0 && lane < 8) {
        int y = wsum[lane];
#pragma unroll
        for (int d = 1; d < 8; d <<= 1) {
            int t = __shfl_up_sync(0xffu, y, d);
            if (lane >= d) y += t;
        }
        wsum[lane] = y;
    }
    __syncthreads();
    int excl = x - v + (wid > 0 ? wsum[wid - 1] : 0);
    if (i < N_NODES) g_offsets[i] = excl;
    if (tid == 255) g_blocksum[blockIdx.x] = excl + v;
}

__global__ void k_scan2() {
    const int lane = threadIdx.x;
    int run = 0;
    for (int base = 0; base < SCAN_NB; base += 32) {
        int i = base + lane;
        int v = (i < SCAN_NB) ? g_blocksum[i] : 0;
        int x = v;
#pragma unroll
        for (int d = 1; d < 32; d <<= 1) {
            int t = __shfl_up_sync(0xffffffffu, x, d);
            if (lane >= d) x += t;
        }
        if (i < SCAN_NB) g_blocksum[i] = run + x - v;   // exclusive
        run += __shfl_sync(0xffffffffu, x, 31);
    }
}

__global__ void k_scan3() {
    int i = blockIdx.x * blockDim.x + threadIdx.x;
    if (i < N_NODES) {
        int o = g_offsets[i] + g_blocksum[i >> 8];
        g_offsets[i] = o;
        g_cursor[i] = o;
        int dg = g_degI[i];
        g_dinv[i] = (dg > 0) ? rsqrtf((float)dg) : 0.0f;
    }
    if (i == 0) g_offsets[N_NODES] = N_EDGES;
}

__global__ void k_fill(const void* __restrict__ ei) {
    int is64 = g_is64;
    for (int e = blockIdx.x * blockDim.x + threadIdx.x; e < N_EDGES;
         e += gridDim.x * blockDim.x) {
        int r, c;
        edge_rc(ei, is64, e, r, c);
        int p = atomicAdd(&g_cursor[c], 1);
        g_erow[p] = r;
    }
}

// ---------------- tensor GEMM: h = fp16((x@W^T + b)*dinv[row]) ----------------
// bf16 Markidis split: acc = xh*Wh + xh*Wl + xl*Wh (fp32 accum).
// CTA: 128x128 tile, 512 threads / 16 warps, warp tile 32x32.
__global__ void __launch_bounds__(512, 1)
k_gemm(const float* __restrict__ x, int layer, const float* __restrict__ bvec) {
    extern __shared__ char sm[];
    __nv_bfloat16* xh = (__nv_bfloat16*)(sm + OFF_XH);
    __nv_bfloat16* xl = (__nv_bfloat16*)(sm + OFF_XL);
    __nv_bfloat16* wh = (__nv_bfloat16*)(sm + OFF_WH);
    __nv_bfloat16* wl = (__nv_bfloat16*)(sm + OFF_WL);

    const int tid = threadIdx.x, lane = tid & 31, wid = tid >> 5;
    const int row0 = blockIdx.x * 128;

    // copy precomputed W splits (bf16, no math)
    {
        const uint4* gwh = (const uint4*)(g_wh + layer * D * D);
        const uint4* gwl = (const uint4*)(g_wl + layer * D * D);
        for (int t = tid; t < 2048; t += 512) {
            int r = t >> 4, c8 = (t & 15) * 8;
            *(uint4*)&wh[r * TPITCH + c8] = gwh[t];
            *(uint4*)&wl[r * TPITCH + c8] = gwl[t];
        }
    }
    // load + split x tile
    for (int t = tid; t < 4096; t += 512) {
        int r = t >> 5, c = (t & 31) * 4;
        int gr = row0 + r;
        float4 v = (gr < N_NODES) ? *(const float4*)&x[(size_t)gr * D + c]
                                  : make_float4(0.f, 0.f, 0.f, 0.f);
        __nv_bfloat16 h0 = __float2bfloat16(v.x), h1 = __float2bfloat16(v.y);
        __nv_bfloat16 h2 = __float2bfloat16(v.z), h3 = __float2bfloat16(v.w);
        __nv_bfloat162 hp0 = __halves2bfloat162(h0, h1), hp1 = __halves2bfloat162(h2, h3);
        __nv_bfloat162 lp0 = __halves2bfloat162(__float2bfloat16(v.x - __bfloat162float(h0)),
                                                __float2bfloat16(v.y - __bfloat162float(h1)));
        __nv_bfloat162 lp1 = __halves2bfloat162(__float2bfloat16(v.z - __bfloat162float(h2)),
                                                __float2bfloat16(v.w - __bfloat162float(h3)));
        uint2 ph, pl;
        ph.x = *(unsigned*)&hp0; ph.y = *(unsigned*)&hp1;
        pl.x = *(unsigned*)&lp0; pl.y = *(unsigned*)&lp1;
        *(uint2*)&xh[r * TPITCH + c] = ph;
        *(uint2*)&xl[r * TPITCH + c] = pl;
    }
    if (blockIdx.x == 0 && tid < 2 * D) g_stats[tid] = 0.0f;
    __syncthreads();

    const int wm = wid >> 2;          // 0..3 : rows wm*32 .. +31
    const int wn = wid & 3;           // 0..3 : cols wn*32 .. +31
    const int lrow = lane & 15;
    const int lksh = (lane >> 4) * 8;

    float acc[2][4][4];
#pragma unroll
    for (int mi = 0; mi < 2; mi++)
#pragma unroll
        for (int ni = 0; ni < 4; ni++)
#pragma unroll
            for (int j = 0; j < 4; j++) acc[mi][ni][j] = 0.0f;

    const uint32_t sxh = smem_u32(xh), sxl = smem_u32(xl);
    const uint32_t swh = smem_u32(wh), swl = smem_u32(wl);

#pragma unroll
    for (int pass = 0; pass < 3; pass++) {
        const uint32_t abase = (pass == 2) ? sxl : sxh;
        const uint32_t bbase = (pass == 1) ? swl : swh;
#pragma unroll
        for (int k0 = 0; k0 < 128; k0 += 16) {
            uint32_t af[2][4];
#pragma unroll
            for (int mi = 0; mi < 2; mi++) {
                uint32_t a = abase +
                    (uint32_t)(((wm * 32 + mi * 16 + lrow) * TPITCH + k0 + lksh) * 2);
                ldm_x4(af[mi][0], af[mi][1], af[mi][2], af[mi][3], a);
            }
            uint32_t bf[2][4];
#pragma unroll
            for (int nh = 0; nh < 2; nh++) {
                uint32_t a = bbase +
                    (uint32_t)(((wn * 32 + nh * 16 + lrow) * TPITCH + k0 + lksh) * 2);
                ldm_x4(bf[nh][0], bf[nh][1], bf[nh][2], bf[nh][3], a);
            }
#pragma unroll
            for (int mi = 0; mi < 2; mi++)
#pragma unroll
                for (int ni = 0; ni < 4; ni++) {
                    int nh = ni >> 1, nl = ni & 1;
                    mma_bf16(acc[mi][ni][0], acc[mi][ni][1], acc[mi][ni][2], acc[mi][ni][3],
                             af[mi][0], af[mi][1], af[mi][2], af[mi][3],
                             bf[nh][nl], bf[nh][nl + 2]);
                }
        }
    }

    // epilogue: (acc + bias) * dinv[row] -> fp16 pairs
    const int g = lane >> 2, tg = lane & 3;
    uint32_t* hw = (uint32_t*)g_h;
#pragma unroll
    for (int mi = 0; mi < 2; mi++) {
        int r0g = row0 + wm * 32 + mi * 16 + g;
        int r1g = r0g + 8;
        float dv0 = (r0g < N_NODES) ? g_dinv[r0g] : 0.0f;
        float dv1 = (r1g < N_NODES) ? g_dinv[r1g] : 0.0f;
#pragma unroll
        for (int ni = 0; ni < 4; ni++) {
            int c = wn * 32 + ni * 8 + 2 * tg;
            float b0 = bvec[c], b1 = bvec[c + 1];
            if (r0g < N_NODES) {
                __half2 p = __floats2half2_rn((acc[mi][ni][0] + b0) * dv0,
                                              (acc[mi][ni][1] + b1) * dv0);
                hw[(size_t)r0g * 64 + (c >> 1)] = *(uint32_t*)&p;
            }
            if (r1g < N_NODES) {
                __half2 p = __floats2half2_rn((acc[mi][ni][2] + b0) * dv1,
                                              (acc[mi][ni][3] + b1) * dv1);
                hw[(size_t)r1g * 64 + (c >> 1)] = *(uint32_t*)&p;
            }
        }
    }
}

// ---------------- gather: agg[n] = dinv[n] * sum_{e: col=n} h[row_e]; fused BN stats ----------------
// (R8-proven structure: 32 lanes per row, uint2 loads, one edge per iteration)
__global__ void k_gather() {
    const int lane = threadIdx.x & 31;
    const int warp = threadIdx.x >> 5;
    const int gw   = blockIdx.x * 8 + warp;
    const int nw   = gridDim.x * 8;
    const uint2* __restrict__ hp = g_h;
    float4* ap = (float4*)g_agg;

    float s0 = 0.f, s1 = 0.f, s2 = 0.f, s3 = 0.f;
    float q0 = 0.f, q1 = 0.f, q2 = 0.f, q3 = 0.f;

    for (int node = gw; node < N_NODES; node += nw) {
        int st = g_offsets[node];
        int en = g_offsets[node + 1];
        float4 acc = make_float4(0.f, 0.f, 0.f, 0.f);
        for (int i = st; i < en; i += 32) {
            int idx = 0;
            if (i + lane < en) idx = g_erow[i + lane];
            int n = min(32, en - i);
#pragma unroll 4
            for (int j = 0; j < n; j++) {
                int r = __shfl_sync(0xffffffffu, idx, j);
                uint2 v = hp[(size_t)r * 32 + lane];
                __half2 a = *reinterpret_cast<__half2*>(&v.x);
                __half2 b = *reinterpret_cast<__half2*>(&v.y);
                float2 f0 = __half22float2(a);
                float2 f1 = __half22float2(b);
                acc.x += f0.x; acc.y += f0.y; acc.z += f1.x; acc.w += f1.y;
            }
        }
        float dc = g_dinv[node];
        acc.x *= dc; acc.y *= dc; acc.z *= dc; acc.w *= dc;
        ap[node * 32 + lane] = acc;
        s0 += acc.x; s1 += acc.y; s2 += acc.z; s3 += acc.w;
        q0 += acc.x * acc.x; q1 += acc.y * acc.y;
        q2 += acc.z * acc.z; q3 += acc.w * acc.w;
    }

    __shared__ float ssum[128], ssq[128];
    if (threadIdx.x < 128) { ssum[threadIdx.x] = 0.f; ssq[threadIdx.x] = 0.f; }
    __syncthreads();
    int c = lane * 4;
    atomicAdd(&ssum[c + 0], s0); atomicAdd(&ssum[c + 1], s1);
    atomicAdd(&ssum[c + 2], s2); atomicAdd(&ssum[c + 3], s3);
    atomicAdd(&ssq[c + 0], q0); atomicAdd(&ssq[c + 1], q1);
    atomicAdd(&ssq[c + 2], q2); atomicAdd(&ssq[c + 3], q3);
    __syncthreads();
    if (threadIdx.x < 128) {
        atomicAdd(&g_stats[threadIdx.x], ssum[threadIdx.x]);
        atomicAdd(&g_stats[D + threadIdx.x], ssq[threadIdx.x]);
    }
}

__global__ void k_bnfinal(const float* __restrict__ gamma, const float* __restrict__ beta) {
    int c = threadIdx.x;
    const float inv_n = 1.0f / (float)N_NODES;
    float mu  = g_stats[c] * inv_n;
    float var = g_stats[D + c] * inv_n - mu * mu;
    float sc  = gamma[c] * rsqrtf(var + BN_EPS);
    g_bn[c]     = sc;
    g_bn[D + c] = beta[c] - mu * sc;
}

__global__ void k_apply(const float* __restrict__ xsrc, float* __restrict__ xdst) {
    int i = blockIdx.x * blockDim.x + threadIdx.x;
    if (i >= N_NODES * 32) return;
    int cq = i & 31;
    float4 a  = ((const float4*)g_agg)[i];
    float4 xv = ((const float4*)xsrc)[i];
    float4 sc = ((const float4*)g_bn)[cq];
    float4 sh = ((const float4*)(g_bn + D))[cq];
    float4 o;
    o.x = xv.x + fmaxf(fmaf(a.x, sc.x, sh.x), 0.f);
    o.y = xv.y + fmaxf(fmaf(a.y, sc.y, sh.y), 0.f);
    o.z = xv.z + fmaxf(fmaf(a.z, sc.z, sh.z), 0.f);
    o.w = xv.w + fmaxf(fmaf(a.w, sc.w, sh.w), 0.f);
    ((float4*)xdst)[i] = o;
}

// ---------------- launch ----------------
extern "C" void kernel_launch(void* const* d_in, const int* in_sizes, int n_in,
                              void* d_out, int out_size) {
    const float* x     = (const float*)d_in[0];
    const void*  ei    = d_in[1];
    const float* W     = (const float*)d_in[2];
    const float* bvec  = (const float*)d_in[3];
    const float* gamma = (const float*)d_in[4];
    const float* beta  = (const float*)d_in[5];
    float* out = (float*)d_out;

    cudaFuncSetAttribute(k_gemm, cudaFuncAttributeMaxDynamicSharedMemorySize, GEMM_SMEM);

    k_pre<<<160, 256>>>((const unsigned long long*)ei);      // 0
    k_wsplit<<<(NL * D * D + 511) / 512, 512>>>(W);          // 1
    k_hist<<<1024, 256>>>(ei);                               // 2
    k_scan1<<<SCAN_NB, 256>>>();                             // 3
    k_scan2<<<1, 32>>>();                                    // 4
    k_scan3<<<(N_NODES + 255) / 256, 256>>>();               // 5

    const float* xin = x;
    const int gemm_blocks  = (N_NODES + 127) / 128;          // 391
    const int apply_blocks = (N_NODES * 32 + 255) / 256;
    const int gather_blocks = 148 * 8;                       // 1184: one full wave

    for (int l = 0; l < NL; l++) {
        k_gemm<<<gemm_blocks, 512, GEMM_SMEM>>>(xin, l, bvec + l * D);
        if (l == 0) k_fill<<<1024, 256>>>(ei);
        k_gather<<<gather_blocks, 256>>>();
        k_bnfinal<<<1, 128>>>(gamma + l * D, beta + l * D);
        k_apply<<<apply_blocks, 256>>>(xin, out);
        xin = out;
    }
}

// round 15
// speedup vs baseline: 1.1354x; 1.0301x over previous
#include <cuda_runtime.h>
#include <cuda_fp16.h>
#include <cuda_bf16.h>
#include <cstdint>

#define N_NODES 50000
#define N_EDGES 800000
#define D       128
#define NL      3
#define BN_EPS  1e-5f
#define SCAN_NB 196   // ceil(50000/256)

// ---------------- scratch (no allocations allowed) ----------------
__device__ uint2  g_h[(size_t)N_NODES * 32];   // h rows, fp16 packed (4 cols / uint2)
__device__ uint2  g_agg[(size_t)N_NODES * 32]; // agg rows, fp16 packed (4 cols / uint2)
__device__ float  g_dinv[N_NODES];
__device__ int    g_degI[N_NODES];
__device__ int    g_colcnt[N_NODES];
__device__ int    g_offsets[N_NODES + 1];
__device__ int    g_cursor[N_NODES];
__device__ int    g_erow[N_EDGES];
__device__ int    g_blocksum[SCAN_NB];
__device__ float  g_stats[2 * D];
__device__ float  g_bn[2 * D];
__device__ int    g_is64;
// precomputed bf16 Markidis split of W for all layers
__device__ __nv_bfloat16 g_wh[NL * D * D];
__device__ __nv_bfloat16 g_wl[NL * D * D];

__device__ __forceinline__ uint32_t smem_u32(const void* p) {
    uint32_t a;
    asm("{ .reg .u64 t; cvta.to.shared.u64 t, %1; cvt.u32.u64 %0, t; }" : "=r"(a) : "l"(p));
    return a;
}
__device__ __forceinline__ void ldm_x4(uint32_t& r0, uint32_t& r1, uint32_t& r2,
                                       uint32_t& r3, uint32_t addr) {
    asm volatile("ldmatrix.sync.aligned.m8n8.x4.shared.b16 {%0,%1,%2,%3}, [%4];"
                 : "=r"(r0), "=r"(r1), "=r"(r2), "=r"(r3) : "r"(addr));
}
__device__ __forceinline__ void mma_bf16(float& d0, float& d1, float& d2, float& d3,
                                         uint32_t a0, uint32_t a1, uint32_t a2, uint32_t a3,
                                         uint32_t b0, uint32_t b1) {
    asm volatile("mma.sync.aligned.m16n8k16.row.col.f32.bf16.bf16.f32 "
                 "{%0,%1,%2,%3}, {%4,%5,%6,%7}, {%8,%9}, {%0,%1,%2,%3};"
                 : "+f"(d0), "+f"(d1), "+f"(d2), "+f"(d3)
                 : "r"(a0), "r"(a1), "r"(a2), "r"(a3), "r"(b0), "r"(b1));
}

// smem tiles: row-major [128][136] bf16 (272B stride -> conflict-free ldmatrix)
#define TPITCH 136
#define TILE_B (128 * TPITCH * 2)   // 34816 bytes
#define OFF_XH 0
#define OFF_XL (OFF_XH + TILE_B)
#define OFF_WH (OFF_XL + TILE_B)
#define OFF_WL (OFF_WH + TILE_B)
#define GEMM_SMEM (4 * TILE_B)      // 139264 bytes

// ---------------- preprocessing (zero counters + dtype sniff + W split, fused) ----------------
__global__ void k_pre(const unsigned long long* __restrict__ ei,
                      const float* __restrict__ W) {
    int gtid = blockIdx.x * blockDim.x + threadIdx.x;
    int nt = gridDim.x * blockDim.x;
    for (int i = gtid; i < N_NODES; i += nt) {
        g_degI[i] = 0;
        g_colcnt[i] = 0;
    }
    for (int i = gtid; i < NL * D * D; i += nt) {
        float w = W[i];
        __nv_bfloat16 h = __float2bfloat16(w);
        g_wh[i] = h;
        g_wl[i] = __float2bfloat16(w - __bfloat162float(h));
    }
    if (blockIdx.x == 0 && threadIdx.x < 32) {
        unsigned long long v = ei[threadIdx.x];
        unsigned mask = __ballot_sync(0xffffffffu, (v >> 32) != 0ull);
        if (threadIdx.x == 0) g_is64 = (mask == 0u) ? 1 : 0;
    }
}

__device__ __forceinline__ void edge_rc(const void* ei, int is64, int e, int& r, int& c) {
    if (is64) {
        const long long* p = (const long long*)ei;
        r = (int)p[e];
        c = (int)p[N_EDGES + e];
    } else {
        const int* p = (const int*)ei;
        r = p[e];
        c = p[N_EDGES + e];
    }
}

__global__ void k_hist(const void* __restrict__ ei) {
    int is64 = g_is64;
    for (int e = blockIdx.x * blockDim.x + threadIdx.x; e < N_EDGES;
         e += gridDim.x * blockDim.x) {
        int r, c;
        edge_rc(ei, is64, e, r, c);
        atomicAdd(&g_degI[r], 1);
        atomicAdd(&g_colcnt[c], 1);
    }
}

// ---- 3-stage multi-block exclusive scan of colcnt -> offsets (+cursor,+dinv) ----
__global__ void k_scan1() {
    __shared__ int wsum[8];
    const int tid = threadIdx.x, lane = tid & 31, wid = tid >> 5;
    int i = blockIdx.x * 256 + tid;
    int v = (i < N_NODES) ? g_colcnt[i] : 0;
    int x = v;
#pragma unroll
    for (int d = 1; d < 32; d <<= 1) {
        int t = __shfl_up_sync(0xffffffffu, x, d);
        if (lane >= d) x += t;
    }
    if (lane == 31) wsum[wid] = x;
    __syncthreads();
    if (wid == 0 && lane < 8) {
        int y = wsum[lane];
#pragma unroll
        for (int d = 1; d < 8; d <<= 1) {
            int t = __shfl_up_sync(0xffu, y, d);
            if (lane >= d) y += t;
        }
        wsum[lane] = y;
    }
    __syncthreads();
    int excl = x - v + (wid > 0 ? wsum[wid - 1] : 0);
    if (i < N_NODES) g_offsets[i] = excl;
    if (tid == 255) g_blocksum[blockIdx.x] = excl + v;
}

__global__ void k_scan2() {
    const int lane = threadIdx.x;
    int run = 0;
    for (int base = 0; base < SCAN_NB; base += 32) {
        int i = base + lane;
        int v = (i < SCAN_NB) ? g_blocksum[i] : 0;
        int x = v;
#pragma unroll
        for (int d = 1; d < 32; d <<= 1) {
            int t = __shfl_up_sync(0xffffffffu, x, d);
            if (lane >= d) x += t;
        }
        if (i < SCAN_NB) g_blocksum[i] = run + x - v;   // exclusive
        run += __shfl_sync(0xffffffffu, x, 31);
    }
}

__global__ void k_scan3() {
    int i = blockIdx.x * blockDim.x + threadIdx.x;
    if (i < N_NODES) {
        int o = g_offsets[i] + g_blocksum[i >> 8];
        g_offsets[i] = o;
        g_cursor[i] = o;
        int dg = g_degI[i];
        g_dinv[i] = (dg > 0) ? rsqrtf((float)dg) : 0.0f;
    }
    if (i == 0) g_offsets[N_NODES] = N_EDGES;
}

__global__ void k_fill(const void* __restrict__ ei) {
    int is64 = g_is64;
    for (int e = blockIdx.x * blockDim.x + threadIdx.x; e < N_EDGES;
         e += gridDim.x * blockDim.x) {
        int r, c;
        edge_rc(ei, is64, e, r, c);
        int p = atomicAdd(&g_cursor[c], 1);
        g_erow[p] = r;
    }
}

// ---------------- tensor GEMM: h = fp16((x@W^T + b)*dinv[row]) ----------------
// bf16 Markidis split: acc = xh*Wh + xh*Wl + xl*Wh (fp32 accum).
// CTA: 128x128 tile, 512 threads / 16 warps, warp tile 32x32.
__global__ void __launch_bounds__(512, 1)
k_gemm(const float* __restrict__ x, int layer, const float* __restrict__ bvec) {
    extern __shared__ char sm[];
    __nv_bfloat16* xh = (__nv_bfloat16*)(sm + OFF_XH);
    __nv_bfloat16* xl = (__nv_bfloat16*)(sm + OFF_XL);
    __nv_bfloat16* wh = (__nv_bfloat16*)(sm + OFF_WH);
    __nv_bfloat16* wl = (__nv_bfloat16*)(sm + OFF_WL);

    const int tid = threadIdx.x, lane = tid & 31, wid = tid >> 5;
    const int row0 = blockIdx.x * 128;

    // copy precomputed W splits (bf16, no math)
    {
        const uint4* gwh = (const uint4*)(g_wh + layer * D * D);
        const uint4* gwl = (const uint4*)(g_wl + layer * D * D);
        for (int t = tid; t < 2048; t += 512) {
            int r = t >> 4, c8 = (t & 15) * 8;
            *(uint4*)&wh[r * TPITCH + c8] = gwh[t];
            *(uint4*)&wl[r * TPITCH + c8] = gwl[t];
        }
    }
    // load + split x tile
    for (int t = tid; t < 4096; t += 512) {
        int r = t >> 5, c = (t & 31) * 4;
        int gr = row0 + r;
        float4 v = (gr < N_NODES) ? *(const float4*)&x[(size_t)gr * D + c]
                                  : make_float4(0.f, 0.f, 0.f, 0.f);
        __nv_bfloat16 h0 = __float2bfloat16(v.x), h1 = __float2bfloat16(v.y);
        __nv_bfloat16 h2 = __float2bfloat16(v.z), h3 = __float2bfloat16(v.w);
        __nv_bfloat162 hp0 = __halves2bfloat162(h0, h1), hp1 = __halves2bfloat162(h2, h3);
        __nv_bfloat162 lp0 = __halves2bfloat162(__float2bfloat16(v.x - __bfloat162float(h0)),
                                                __float2bfloat16(v.y - __bfloat162float(h1)));
        __nv_bfloat162 lp1 = __halves2bfloat162(__float2bfloat16(v.z - __bfloat162float(h2)),
                                                __float2bfloat16(v.w - __bfloat162float(h3)));
        uint2 ph, pl;
        ph.x = *(unsigned*)&hp0; ph.y = *(unsigned*)&hp1;
        pl.x = *(unsigned*)&lp0; pl.y = *(unsigned*)&lp1;
        *(uint2*)&xh[r * TPITCH + c] = ph;
        *(uint2*)&xl[r * TPITCH + c] = pl;
    }
    if (blockIdx.x == 0 && tid < 2 * D) g_stats[tid] = 0.0f;
    __syncthreads();

    const int wm = wid >> 2;          // 0..3 : rows wm*32 .. +31
    const int wn = wid & 3;           // 0..3 : cols wn*32 .. +31
    const int lrow = lane & 15;
    const int lksh = (lane >> 4) * 8;

    float acc[2][4][4];
#pragma unroll
    for (int mi = 0; mi < 2; mi++)
#pragma unroll
        for (int ni = 0; ni < 4; ni++)
#pragma unroll
            for (int j = 0; j < 4; j++) acc[mi][ni][j] = 0.0f;

    const uint32_t sxh = smem_u32(xh), sxl = smem_u32(xl);
    const uint32_t swh = smem_u32(wh), swl = smem_u32(wl);

#pragma unroll
    for (int pass = 0; pass < 3; pass++) {
        const uint32_t abase = (pass == 2) ? sxl : sxh;
        const uint32_t bbase = (pass == 1) ? swl : swh;
#pragma unroll
        for (int k0 = 0; k0 < 128; k0 += 16) {
            uint32_t af[2][4];
#pragma unroll
            for (int mi = 0; mi < 2; mi++) {
                uint32_t a = abase +
                    (uint32_t)(((wm * 32 + mi * 16 + lrow) * TPITCH + k0 + lksh) * 2);
                ldm_x4(af[mi][0], af[mi][1], af[mi][2], af[mi][3], a);
            }
            uint32_t bf[2][4];
#pragma unroll
            for (int nh = 0; nh < 2; nh++) {
                uint32_t a = bbase +
                    (uint32_t)(((wn * 32 + nh * 16 + lrow) * TPITCH + k0 + lksh) * 2);
                ldm_x4(bf[nh][0], bf[nh][1], bf[nh][2], bf[nh][3], a);
            }
#pragma unroll
            for (int mi = 0; mi < 2; mi++)
#pragma unroll
                for (int ni = 0; ni < 4; ni++) {
                    int nh = ni >> 1, nl = ni & 1;
                    mma_bf16(acc[mi][ni][0], acc[mi][ni][1], acc[mi][ni][2], acc[mi][ni][3],
                             af[mi][0], af[mi][1], af[mi][2], af[mi][3],
                             bf[nh][nl], bf[nh][nl + 2]);
                }
        }
    }

    // epilogue: (acc + bias) * dinv[row] -> fp16 pairs
    const int g = lane >> 2, tg = lane & 3;
    uint32_t* hw = (uint32_t*)g_h;
#pragma unroll
    for (int mi = 0; mi < 2; mi++) {
        int r0g = row0 + wm * 32 + mi * 16 + g;
        int r1g = r0g + 8;
        float dv0 = (r0g < N_NODES) ? g_dinv[r0g] : 0.0f;
        float dv1 = (r1g < N_NODES) ? g_dinv[r1g] : 0.0f;
#pragma unroll
        for (int ni = 0; ni < 4; ni++) {
            int c = wn * 32 + ni * 8 + 2 * tg;
            float b0 = bvec[c], b1 = bvec[c + 1];
            if (r0g < N_NODES) {
                __half2 p = __floats2half2_rn((acc[mi][ni][0] + b0) * dv0,
                                              (acc[mi][ni][1] + b1) * dv0);
                hw[(size_t)r0g * 64 + (c >> 1)] = *(uint32_t*)&p;
            }
            if (r1g < N_NODES) {
                __half2 p = __floats2half2_rn((acc[mi][ni][2] + b0) * dv1,
                                              (acc[mi][ni][3] + b1) * dv1);
                hw[(size_t)r1g * 64 + (c >> 1)] = *(uint32_t*)&p;
            }
        }
    }
}

// ---------------- gather: agg[n] = fp16(dinv[n] * sum_{e: col=n} h[row_e]); fused BN stats ----------------
// Stats are computed from the ROUNDED (fp16) values so BN normalization in
// k_apply sees exactly the data the stats describe.
__global__ void k_gather() {
    const int lane = threadIdx.x & 31;
    const int warp = threadIdx.x >> 5;
    const int gw   = blockIdx.x * 8 + warp;
    const int nw   = gridDim.x * 8;
    const uint2* __restrict__ hp = g_h;
    uint2* ap = g_agg;

    float s0 = 0.f, s1 = 0.f, s2 = 0.f, s3 = 0.f;
    float q0 = 0.f, q1 = 0.f, q2 = 0.f, q3 = 0.f;

    for (int node = gw; node < N_NODES; node += nw) {
        int st = g_offsets[node];
        int en = g_offsets[node + 1];
        float4 acc = make_float4(0.f, 0.f, 0.f, 0.f);
        for (int i = st; i < en; i += 32) {
            int idx = 0;
            if (i + lane < en) idx = g_erow[i + lane];
            int n = min(32, en - i);
#pragma unroll 4
            for (int j = 0; j < n; j++) {
                int r = __shfl_sync(0xffffffffu, idx, j);
                uint2 v = hp[(size_t)r * 32 + lane];
                __half2 a = *reinterpret_cast<__half2*>(&v.x);
                __half2 b = *reinterpret_cast<__half2*>(&v.y);
                float2 f0 = __half22float2(a);
                float2 f1 = __half22float2(b);
                acc.x += f0.x; acc.y += f0.y; acc.z += f1.x; acc.w += f1.y;
            }
        }
        float dc = g_dinv[node];
        // round to fp16, then use the ROUNDED values for both store and stats
        __half2 p0 = __floats2half2_rn(acc.x * dc, acc.y * dc);
        __half2 p1 = __floats2half2_rn(acc.z * dc, acc.w * dc);
        uint2 pk;
        pk.x = *(unsigned*)&p0;
        pk.y = *(unsigned*)&p1;
        ap[(size_t)node * 32 + lane] = pk;
        float2 r0 = __half22float2(p0);
        float2 r1 = __half22float2(p1);
        s0 += r0.x; s1 += r0.y; s2 += r1.x; s3 += r1.y;
        q0 += r0.x * r0.x; q1 += r0.y * r0.y;
        q2 += r1.x * r1.x; q3 += r1.y * r1.y;
    }

    __shared__ float ssum[128], ssq[128];
    if (threadIdx.x < 128) { ssum[threadIdx.x] = 0.f; ssq[threadIdx.x] = 0.f; }
    __syncthreads();
    int c = lane * 4;
    atomicAdd(&ssum[c + 0], s0); atomicAdd(&ssum[c + 1], s1);
    atomicAdd(&ssum[c + 2], s2); atomicAdd(&ssum[c + 3], s3);
    atomicAdd(&ssq[c + 0], q0); atomicAdd(&ssq[c + 1], q1);
    atomicAdd(&ssq[c + 2], q2); atomicAdd(&ssq[c + 3], q3);
    __syncthreads();
    if (threadIdx.x < 128) {
        atomicAdd(&g_stats[threadIdx.x], ssum[threadIdx.x]);
        atomicAdd(&g_stats[D + threadIdx.x], ssq[threadIdx.x]);
    }
}

__global__ void k_bnfinal(const float* __restrict__ gamma, const float* __restrict__ beta) {
    int c = threadIdx.x;
    const float inv_n = 1.0f / (float)N_NODES;
    float mu  = g_stats[c] * inv_n;
    float var = g_stats[D + c] * inv_n - mu * mu;
    float sc  = gamma[c] * rsqrtf(var + BN_EPS);
    g_bn[c]     = sc;
    g_bn[D + c] = beta[c] - mu * sc;
}

__global__ void k_apply(const float* __restrict__ xsrc, float* __restrict__ xdst) {
    int i = blockIdx.x * blockDim.x + threadIdx.x;
    if (i >= N_NODES * 32) return;
    int cq = i & 31;
    uint2 av = g_agg[i];
    __half2 a0 = *reinterpret_cast<__half2*>(&av.x);
    __half2 a1 = *reinterpret_cast<__half2*>(&av.y);
    float2 f0 = __half22float2(a0);
    float2 f1 = __half22float2(a1);
    float4 xv = ((const float4*)xsrc)[i];
    float4 sc = ((const float4*)g_bn)[cq];
    float4 sh = ((const float4*)(g_bn + D))[cq];
    float4 o;
    o.x = xv.x + fmaxf(fmaf(f0.x, sc.x, sh.x), 0.f);
    o.y = xv.y + fmaxf(fmaf(f0.y, sc.y, sh.y), 0.f);
    o.z = xv.z + fmaxf(fmaf(f1.x, sc.z, sh.z), 0.f);
    o.w = xv.w + fmaxf(fmaf(f1.y, sc.w, sh.w), 0.f);
    ((float4*)xdst)[i] = o;
}

// ---------------- launch ----------------
extern "C" void kernel_launch(void* const* d_in, const int* in_sizes, int n_in,
                              void* d_out, int out_size) {
    const float* x     = (const float*)d_in[0];
    const void*  ei    = d_in[1];
    const float* W     = (const float*)d_in[2];
    const float* bvec  = (const float*)d_in[3];
    const float* gamma = (const float*)d_in[4];
    const float* beta  = (const float*)d_in[5];
    float* out = (float*)d_out;

    cudaFuncSetAttribute(k_gemm, cudaFuncAttributeMaxDynamicSharedMemorySize, GEMM_SMEM);

    k_pre<<<160, 256>>>((const unsigned long long*)ei, W);   // 0 (zero + sniff + wsplit)
    k_hist<<<1024, 256>>>(ei);                               // 1
    k_scan1<<<SCAN_NB, 256>>>();                             // 2
    k_scan2<<<1, 32>>>();                                    // 3
    k_scan3<<<(N_NODES + 255) / 256, 256>>>();               // 4

    const float* xin = x;
    const int gemm_blocks  = (N_NODES + 127) / 128;          // 391
    const int apply_blocks = (N_NODES * 32 + 255) / 256;
    const int gather_blocks = 148 * 8;                       // 1184: one full wave

    for (int l = 0; l < NL; l++) {
        k_gemm<<<gemm_blocks, 512, GEMM_SMEM>>>(xin, l, bvec + l * D);
        if (l == 0) k_fill<<<1024, 256>>>(ei);
        k_gather<<<gather_blocks, 256>>>();
        k_bnfinal<<<1, 128>>>(gamma + l * D, beta + l * D);
        k_apply<<<apply_blocks, 256>>>(xin, out);
        xin = out;
    }
}

// round 16
// speedup vs baseline: 1.1524x; 1.0150x over previous
#include <cuda_runtime.h>
#include <cuda_fp16.h>
#include <cuda_bf16.h>
#include <cstdint>

#define N_NODES 50000
#define N_EDGES 800000
#define D       128
#define NL      3
#define BN_EPS  1e-5f
#define SCAN_NB 196   // ceil(50000/256)

// ---------------- scratch (no allocations allowed) ----------------
__device__ uint2  g_h[(size_t)N_NODES * 32];   // h rows, fp16 packed (4 cols / uint2)
__device__ uint2  g_agg[(size_t)N_NODES * 32]; // agg rows, fp16 packed (4 cols / uint2)
__device__ float  g_dinv[N_NODES];
__device__ int    g_degI[N_NODES];
__device__ int    g_colcnt[N_NODES];
__device__ int    g_offsets[N_NODES + 1];
__device__ int    g_cursor[N_NODES];
__device__ int    g_erow[N_EDGES];
__device__ int    g_blocksum[SCAN_NB];         // raw per-block totals
__device__ float  g_stats[2 * D];
__device__ float  g_bn[2 * D];
__device__ int    g_is64;
// precomputed bf16 Markidis split of W for all layers
__device__ __nv_bfloat16 g_wh[NL * D * D];
__device__ __nv_bfloat16 g_wl[NL * D * D];

__device__ __forceinline__ uint32_t smem_u32(const void* p) {
    uint32_t a;
    asm("{ .reg .u64 t; cvta.to.shared.u64 t, %1; cvt.u32.u64 %0, t; }" : "=r"(a) : "l"(p));
    return a;
}
__device__ __forceinline__ void ldm_x4(uint32_t& r0, uint32_t& r1, uint32_t& r2,
                                       uint32_t& r3, uint32_t addr) {
    asm volatile("ldmatrix.sync.aligned.m8n8.x4.shared.b16 {%0,%1,%2,%3}, [%4];"
                 : "=r"(r0), "=r"(r1), "=r"(r2), "=r"(r3) : "r"(addr));
}
__device__ __forceinline__ void mma_bf16(float& d0, float& d1, float& d2, float& d3,
                                         uint32_t a0, uint32_t a1, uint32_t a2, uint32_t a3,
                                         uint32_t b0, uint32_t b1) {
    asm volatile("mma.sync.aligned.m16n8k16.row.col.f32.bf16.bf16.f32 "
                 "{%0,%1,%2,%3}, {%4,%5,%6,%7}, {%8,%9}, {%0,%1,%2,%3};"
                 : "+f"(d0), "+f"(d1), "+f"(d2), "+f"(d3)
                 : "r"(a0), "r"(a1), "r"(a2), "r"(a3), "r"(b0), "r"(b1));
}

// smem tiles: row-major [128][136] bf16 (272B stride -> conflict-free ldmatrix)
#define TPITCH 136
#define TILE_B (128 * TPITCH * 2)   // 34816 bytes
#define OFF_XH 0
#define OFF_XL (OFF_XH + TILE_B)
#define OFF_WH (OFF_XL + TILE_B)
#define OFF_WL (OFF_WH + TILE_B)
#define GEMM_SMEM (4 * TILE_B)      // 139264 bytes

// ---------------- preprocessing (zero counters + dtype sniff + W split, fused) ----------------
__global__ void k_pre(const unsigned long long* __restrict__ ei,
                      const float* __restrict__ W) {
    int gtid = blockIdx.x * blockDim.x + threadIdx.x;
    int nt = gridDim.x * blockDim.x;
    for (int i = gtid; i < N_NODES; i += nt) {
        g_degI[i] = 0;
        g_colcnt[i] = 0;
    }
    for (int i = gtid; i < NL * D * D; i += nt) {
        float w = W[i];
        __nv_bfloat16 h = __float2bfloat16(w);
        g_wh[i] = h;
        g_wl[i] = __float2bfloat16(w - __bfloat162float(h));
    }
    if (blockIdx.x == 0 && threadIdx.x < 32) {
        unsigned long long v = ei[threadIdx.x];
        unsigned mask = __ballot_sync(0xffffffffu, (v >> 32) != 0ull);
        if (threadIdx.x == 0) g_is64 = (mask == 0u) ? 1 : 0;
    }
}

__device__ __forceinline__ void edge_rc(const void* ei, int is64, int e, int& r, int& c) {
    if (is64) {
        const long long* p = (const long long*)ei;
        r = (int)p[e];
        c = (int)p[N_EDGES + e];
    } else {
        const int* p = (const int*)ei;
        r = p[e];
        c = p[N_EDGES + e];
    }
}

__global__ void k_hist(const void* __restrict__ ei) {
    int is64 = g_is64;
    for (int e = blockIdx.x * blockDim.x + threadIdx.x; e < N_EDGES;
         e += gridDim.x * blockDim.x) {
        int r, c;
        edge_rc(ei, is64, e, r, c);
        atomicAdd(&g_degI[r], 1);
        atomicAdd(&g_colcnt[c], 1);
    }
}

// ---- 2-stage scan: per-block exclusive + raw totals; prefix folded into stage 2 ----
__global__ void k_scan1() {
    __shared__ int wsum[8];
    const int tid = threadIdx.x, lane = tid & 31, wid = tid >> 5;
    int i = blockIdx.x * 256 + tid;
    int v = (i < N_NODES) ? g_colcnt[i] : 0;
    int x = v;
#pragma unroll
    for (int d = 1; d < 32; d <<= 1) {
        int t = __shfl_up_sync(0xffffffffu, x, d);
        if (lane >= d) x += t;
    }
    if (lane == 31) wsum[wid] = x;
    __syncthreads();
    if (wid == 0 && lane < 8) {
        int y = wsum[lane];
#pragma unroll
        for (int d = 1; d < 8; d <<= 1) {
            int t = __shfl_up_sync(0xffu, y, d);
            if (lane >= d) y += t;
        }
        wsum[lane] = y;
    }
    __syncthreads();
    int excl = x - v + (wid > 0 ? wsum[wid - 1] : 0);
    if (i < N_NODES) g_offsets[i] = excl;
    if (tid == 255) g_blocksum[blockIdx.x] = excl + v;   // raw block total
}

// stage 2: each block computes its prefix over raw blocksums, then finalizes
// offsets/cursor/dinv for its 256-node chunk. (replaces the serial k_scan2)
__global__ void k_scan3() {
    __shared__ int wred[8];
    const int tid = threadIdx.x, lane = tid & 31, wid = tid >> 5;
    const int chunk = blockIdx.x;

    // block-reduce: prefix = sum of blocksum[b] for b < chunk
    int v = (tid < chunk) ? g_blocksum[tid] : 0;   // chunk <= 195 < 256
#pragma unroll
    for (int d = 16; d > 0; d >>= 1)
        v += __shfl_down_sync(0xffffffffu, v, d);
    if (lane == 0) wred[wid] = v;
    __syncthreads();
    if (wid == 0) {
        int y = (lane < 8) ? wred[lane] : 0;
#pragma unroll
        for (int d = 4; d > 0; d >>= 1)
            y += __shfl_down_sync(0xffffffffu, y, d);
        if (lane == 0) wred[0] = y;
    }
    __syncthreads();
    const int prefix = wred[0];

    int i = chunk * 256 + tid;
    if (i < N_NODES) {
        int o = g_offsets[i] + prefix;
        g_offsets[i] = o;
        g_cursor[i] = o;
        int dg = g_degI[i];
        g_dinv[i] = (dg > 0) ? rsqrtf((float)dg) : 0.0f;
    }
    if (i == 0) g_offsets[N_NODES] = N_EDGES;
}

__global__ void k_fill(const void* __restrict__ ei) {
    int is64 = g_is64;
    for (int e = blockIdx.x * blockDim.x + threadIdx.x; e < N_EDGES;
         e += gridDim.x * blockDim.x) {
        int r, c;
        edge_rc(ei, is64, e, r, c);
        int p = atomicAdd(&g_cursor[c], 1);
        g_erow[p] = r;
    }
}

// ---------------- tensor GEMM: h = fp16((x@W^T + b)*dinv[row]) ----------------
// bf16 Markidis split: acc = xh*Wh + xh*Wl + xl*Wh (fp32 accum).
// CTA: 128x128 tile, 512 threads / 16 warps, warp tile 32x32.
__global__ void __launch_bounds__(512, 1)
k_gemm(const float* __restrict__ x, int layer, const float* __restrict__ bvec) {
    extern __shared__ char sm[];
    __nv_bfloat16* xh = (__nv_bfloat16*)(sm + OFF_XH);
    __nv_bfloat16* xl = (__nv_bfloat16*)(sm + OFF_XL);
    __nv_bfloat16* wh = (__nv_bfloat16*)(sm + OFF_WH);
    __nv_bfloat16* wl = (__nv_bfloat16*)(sm + OFF_WL);

    const int tid = threadIdx.x, lane = tid & 31, wid = tid >> 5;
    const int row0 = blockIdx.x * 128;

    // copy precomputed W splits (bf16, no math)
    {
        const uint4* gwh = (const uint4*)(g_wh + layer * D * D);
        const uint4* gwl = (const uint4*)(g_wl + layer * D * D);
        for (int t = tid; t < 2048; t += 512) {
            int r = t >> 4, c8 = (t & 15) * 8;
            *(uint4*)&wh[r * TPITCH + c8] = gwh[t];
            *(uint4*)&wl[r * TPITCH + c8] = gwl[t];
        }
    }
    // load + split x tile
    for (int t = tid; t < 4096; t += 512) {
        int r = t >> 5, c = (t & 31) * 4;
        int gr = row0 + r;
        float4 v = (gr < N_NODES) ? *(const float4*)&x[(size_t)gr * D + c]
                                  : make_float4(0.f, 0.f, 0.f, 0.f);
        __nv_bfloat16 h0 = __float2bfloat16(v.x), h1 = __float2bfloat16(v.y);
        __nv_bfloat16 h2 = __float2bfloat16(v.z), h3 = __float2bfloat16(v.w);
        __nv_bfloat162 hp0 = __halves2bfloat162(h0, h1), hp1 = __halves2bfloat162(h2, h3);
        __nv_bfloat162 lp0 = __halves2bfloat162(__float2bfloat16(v.x - __bfloat162float(h0)),
                                                __float2bfloat16(v.y - __bfloat162float(h1)));
        __nv_bfloat162 lp1 = __halves2bfloat162(__float2bfloat16(v.z - __bfloat162float(h2)),
                                                __float2bfloat16(v.w - __bfloat162float(h3)));
        uint2 ph, pl;
        ph.x = *(unsigned*)&hp0; ph.y = *(unsigned*)&hp1;
        pl.x = *(unsigned*)&lp0; pl.y = *(unsigned*)&lp1;
        *(uint2*)&xh[r * TPITCH + c] = ph;
        *(uint2*)&xl[r * TPITCH + c] = pl;
    }
    if (blockIdx.x == 0 && tid < 2 * D) g_stats[tid] = 0.0f;
    __syncthreads();

    const int wm = wid >> 2;          // 0..3 : rows wm*32 .. +31
    const int wn = wid & 3;           // 0..3 : cols wn*32 .. +31
    const int lrow = lane & 15;
    const int lksh = (lane >> 4) * 8;

    float acc[2][4][4];
#pragma unroll
    for (int mi = 0; mi < 2; mi++)
#pragma unroll
        for (int ni = 0; ni < 4; ni++)
#pragma unroll
            for (int j = 0; j < 4; j++) acc[mi][ni][j] = 0.0f;

    const uint32_t sxh = smem_u32(xh), sxl = smem_u32(xl);
    const uint32_t swh = smem_u32(wh), swl = smem_u32(wl);

#pragma unroll
    for (int pass = 0; pass < 3; pass++) {
        const uint32_t abase = (pass == 2) ? sxl : sxh;
        const uint32_t bbase = (pass == 1) ? swl : swh;
#pragma unroll
        for (int k0 = 0; k0 < 128; k0 += 16) {
            uint32_t af[2][4];
#pragma unroll
            for (int mi = 0; mi < 2; mi++) {
                uint32_t a = abase +
                    (uint32_t)(((wm * 32 + mi * 16 + lrow) * TPITCH + k0 + lksh) * 2);
                ldm_x4(af[mi][0], af[mi][1], af[mi][2], af[mi][3], a);
            }
            uint32_t bf[2][4];
#pragma unroll
            for (int nh = 0; nh < 2; nh++) {
                uint32_t a = bbase +
                    (uint32_t)(((wn * 32 + nh * 16 + lrow) * TPITCH + k0 + lksh) * 2);
                ldm_x4(bf[nh][0], bf[nh][1], bf[nh][2], bf[nh][3], a);
            }
#pragma unroll
            for (int mi = 0; mi < 2; mi++)
#pragma unroll
                for (int ni = 0; ni < 4; ni++) {
                    int nh = ni >> 1, nl = ni & 1;
                    mma_bf16(acc[mi][ni][0], acc[mi][ni][1], acc[mi][ni][2], acc[mi][ni][3],
                             af[mi][0], af[mi][1], af[mi][2], af[mi][3],
                             bf[nh][nl], bf[nh][nl + 2]);
                }
        }
    }

    // epilogue: (acc + bias) * dinv[row] -> fp16 pairs
    const int g = lane >> 2, tg = lane & 3;
    uint32_t* hw = (uint32_t*)g_h;
#pragma unroll
    for (int mi = 0; mi < 2; mi++) {
        int r0g = row0 + wm * 32 + mi * 16 + g;
        int r1g = r0g + 8;
        float dv0 = (r0g < N_NODES) ? g_dinv[r0g] : 0.0f;
        float dv1 = (r1g < N_NODES) ? g_dinv[r1g] : 0.0f;
#pragma unroll
        for (int ni = 0; ni < 4; ni++) {
            int c = wn * 32 + ni * 8 + 2 * tg;
            float b0 = bvec[c], b1 = bvec[c + 1];
            if (r0g < N_NODES) {
                __half2 p = __floats2half2_rn((acc[mi][ni][0] + b0) * dv0,
                                              (acc[mi][ni][1] + b1) * dv0);
                hw[(size_t)r0g * 64 + (c >> 1)] = *(uint32_t*)&p;
            }
            if (r1g < N_NODES) {
                __half2 p = __floats2half2_rn((acc[mi][ni][2] + b0) * dv1,
                                              (acc[mi][ni][3] + b1) * dv1);
                hw[(size_t)r1g * 64 + (c >> 1)] = *(uint32_t*)&p;
            }
        }
    }
}

// ---------------- gather: agg[n] = fp16(dinv[n] * sum_{e: col=n} h[row_e]); fused BN stats ----------------
// Stats are computed from the ROUNDED (fp16) values so BN normalization in
// k_apply sees exactly the data the stats describe.
__global__ void k_gather() {
    const int lane = threadIdx.x & 31;
    const int warp = threadIdx.x >> 5;
    const int gw   = blockIdx.x * 8 + warp;
    const int nw   = gridDim.x * 8;
    const uint2* __restrict__ hp = g_h;
    uint2* ap = g_agg;

    float s0 = 0.f, s1 = 0.f, s2 = 0.f, s3 = 0.f;
    float q0 = 0.f, q1 = 0.f, q2 = 0.f, q3 = 0.f;

    for (int node = gw; node < N_NODES; node += nw) {
        int st = g_offsets[node];
        int en = g_offsets[node + 1];
        float4 acc = make_float4(0.f, 0.f, 0.f, 0.f);
        for (int i = st; i < en; i += 32) {
            int idx = 0;
            if (i + lane < en) idx = g_erow[i + lane];
            int n = min(32, en - i);
#pragma unroll 4
            for (int j = 0; j < n; j++) {
                int r = __shfl_sync(0xffffffffu, idx, j);
                uint2 v = hp[(size_t)r * 32 + lane];
                __half2 a = *reinterpret_cast<__half2*>(&v.x);
                __half2 b = *reinterpret_cast<__half2*>(&v.y);
                float2 f0 = __half22float2(a);
                float2 f1 = __half22float2(b);
                acc.x += f0.x; acc.y += f0.y; acc.z += f1.x; acc.w += f1.y;
            }
        }
        float dc = g_dinv[node];
        // round to fp16, then use the ROUNDED values for both store and stats
        __half2 p0 = __floats2half2_rn(acc.x * dc, acc.y * dc);
        __half2 p1 = __floats2half2_rn(acc.z * dc, acc.w * dc);
        uint2 pk;
        pk.x = *(unsigned*)&p0;
        pk.y = *(unsigned*)&p1;
        ap[(size_t)node * 32 + lane] = pk;
        float2 r0 = __half22float2(p0);
        float2 r1 = __half22float2(p1);
        s0 += r0.x; s1 += r0.y; s2 += r1.x; s3 += r1.y;
        q0 += r0.x * r0.x; q1 += r0.y * r0.y;
        q2 += r1.x * r1.x; q3 += r1.y * r1.y;
    }

    __shared__ float ssum[128], ssq[128];
    if (threadIdx.x < 128) { ssum[threadIdx.x] = 0.f; ssq[threadIdx.x] = 0.f; }
    __syncthreads();
    int c = lane * 4;
    atomicAdd(&ssum[c + 0], s0); atomicAdd(&ssum[c + 1], s1);
    atomicAdd(&ssum[c + 2], s2); atomicAdd(&ssum[c + 3], s3);
    atomicAdd(&ssq[c + 0], q0); atomicAdd(&ssq[c + 1], q1);
    atomicAdd(&ssq[c + 2], q2); atomicAdd(&ssq[c + 3], q3);
    __syncthreads();
    if (threadIdx.x < 128) {
        atomicAdd(&g_stats[threadIdx.x], ssum[threadIdx.x]);
        atomicAdd(&g_stats[D + threadIdx.x], ssq[threadIdx.x]);
    }
}

__global__ void k_bnfinal(const float* __restrict__ gamma, const float* __restrict__ beta) {
    int c = threadIdx.x;
    const float inv_n = 1.0f / (float)N_NODES;
    float mu  = g_stats[c] * inv_n;
    float var = g_stats[D + c] * inv_n - mu * mu;
    float sc  = gamma[c] * rsqrtf(var + BN_EPS);
    g_bn[c]     = sc;
    g_bn[D + c] = beta[c] - mu * sc;
}

__global__ void k_apply(const float* __restrict__ xsrc, float* __restrict__ xdst) {
    int i = blockIdx.x * blockDim.x + threadIdx.x;
    if (i >= N_NODES * 32) return;
    int cq = i & 31;
    uint2 av = g_agg[i];
    __half2 a0 = *reinterpret_cast<__half2*>(&av.x);
    __half2 a1 = *reinterpret_cast<__half2*>(&av.y);
    float2 f0 = __half22float2(a0);
    float2 f1 = __half22float2(a1);
    float4 xv = ((const float4*)xsrc)[i];
    float4 sc = ((const float4*)g_bn)[cq];
    float4 sh = ((const float4*)(g_bn + D))[cq];
    float4 o;
    o.x = xv.x + fmaxf(fmaf(f0.x, sc.x, sh.x), 0.f);
    o.y = xv.y + fmaxf(fmaf(f0.y, sc.y, sh.y), 0.f);
    o.z = xv.z + fmaxf(fmaf(f1.x, sc.z, sh.z), 0.f);
    o.w = xv.w + fmaxf(fmaf(f1.y, sc.w, sh.w), 0.f);
    ((float4*)xdst)[i] = o;
}

// ---------------- launch ----------------
extern "C" void kernel_launch(void* const* d_in, const int* in_sizes, int n_in,
                              void* d_out, int out_size) {
    const float* x     = (const float*)d_in[0];
    const void*  ei    = d_in[1];
    const float* W     = (const float*)d_in[2];
    const float* bvec  = (const float*)d_in[3];
    const float* gamma = (const float*)d_in[4];
    const float* beta  = (const float*)d_in[5];
    float* out = (float*)d_out;

    cudaFuncSetAttribute(k_gemm, cudaFuncAttributeMaxDynamicSharedMemorySize, GEMM_SMEM);

    k_pre<<<160, 256>>>((const unsigned long long*)ei, W);   // 0 (zero + sniff + wsplit)
    k_hist<<<1024, 256>>>(ei);                               // 1
    k_scan1<<<SCAN_NB, 256>>>();                             // 2
    k_scan3<<<SCAN_NB, 256>>>();                             // 3 (prefix folded in)

    const float* xin = x;
    const int gemm_blocks  = (N_NODES + 127) / 128;          // 391
    const int apply_blocks = (N_NODES * 32 + 255) / 256;
    const int gather_blocks = 148 * 8;                       // 1184: one full wave

    for (int l = 0; l < NL; l++) {
        k_gemm<<<gemm_blocks, 512, GEMM_SMEM>>>(xin, l, bvec + l * D);
        if (l == 0) k_fill<<<1024, 256>>>(ei);
        k_gather<<<gather_blocks, 256>>>();
        k_bnfinal<<<1, 128>>>(gamma + l * D, beta + l * D);
        k_apply<<<apply_blocks, 256>>>(xin, out);
        xin = out;
    }
}

// round 17
// speedup vs baseline: 1.1527x; 1.0002x over previous
#include <cuda_runtime.h>
#include <cuda_fp16.h>
#include <cuda_bf16.h>
#include <cstdint>

#define N_NODES 50000
#define N_EDGES 800000
#define D       128
#define NL      3
#define BN_EPS  1e-5f
#define SCAN_NB 196   // ceil(50000/256)
#define GATHER_BLOCKS (148 * 8)

// ---------------- scratch (no allocations allowed) ----------------
__device__ uint2  g_h[(size_t)N_NODES * 32];   // h rows, fp16 packed (4 cols / uint2)
__device__ uint2  g_agg[(size_t)N_NODES * 32]; // agg rows, fp16 packed (4 cols / uint2)
__device__ float  g_dinv[N_NODES];
__device__ int    g_degI[N_NODES];
__device__ int    g_colcnt[N_NODES];
__device__ int    g_offsets[N_NODES + 1];
__device__ int    g_cursor[N_NODES];
__device__ int    g_erow[N_EDGES];
__device__ int    g_blocksum[SCAN_NB];         // raw per-block totals
__device__ float  g_stats[2 * D];
__device__ float  g_bn[2 * D];
__device__ int    g_bnctr;                      // last-block counter for fused bnfinal
__device__ int    g_is64;
// precomputed bf16 Markidis split of W for all layers
__device__ __nv_bfloat16 g_wh[NL * D * D];
__device__ __nv_bfloat16 g_wl[NL * D * D];

__device__ __forceinline__ uint32_t smem_u32(const void* p) {
    uint32_t a;
    asm("{ .reg .u64 t; cvta.to.shared.u64 t, %1; cvt.u32.u64 %0, t; }" : "=r"(a) : "l"(p));
    return a;
}
__device__ __forceinline__ void ldm_x4(uint32_t& r0, uint32_t& r1, uint32_t& r2,
                                       uint32_t& r3, uint32_t addr) {
    asm volatile("ldmatrix.sync.aligned.m8n8.x4.shared.b16 {%0,%1,%2,%3}, [%4];"
                 : "=r"(r0), "=r"(r1), "=r"(r2), "=r"(r3) : "r"(addr));
}
__device__ __forceinline__ void mma_bf16(float& d0, float& d1, float& d2, float& d3,
                                         uint32_t a0, uint32_t a1, uint32_t a2, uint32_t a3,
                                         uint32_t b0, uint32_t b1) {
    asm volatile("mma.sync.aligned.m16n8k16.row.col.f32.bf16.bf16.f32 "
                 "{%0,%1,%2,%3}, {%4,%5,%6,%7}, {%8,%9}, {%0,%1,%2,%3};"
                 : "+f"(d0), "+f"(d1), "+f"(d2), "+f"(d3)
                 : "r"(a0), "r"(a1), "r"(a2), "r"(a3), "r"(b0), "r"(b1));
}

// smem tiles: row-major [128][136] bf16 (272B stride -> conflict-free ldmatrix)
#define TPITCH 136
#define TILE_B (128 * TPITCH * 2)   // 34816 bytes
#define OFF_XH 0
#define OFF_XL (OFF_XH + TILE_B)
#define OFF_WH (OFF_XL + TILE_B)
#define OFF_WL (OFF_WH + TILE_B)
#define GEMM_SMEM (4 * TILE_B)      // 139264 bytes

// ---------------- preprocessing (zero counters + dtype sniff + W split, fused) ----------------
__global__ void k_pre(const unsigned long long* __restrict__ ei,
                      const float* __restrict__ W) {
    int gtid = blockIdx.x * blockDim.x + threadIdx.x;
    int nt = gridDim.x * blockDim.x;
    for (int i = gtid; i < N_NODES; i += nt) {
        g_degI[i] = 0;
        g_colcnt[i] = 0;
    }
    for (int i = gtid; i < NL * D * D; i += nt) {
        float w = W[i];
        __nv_bfloat16 h = __float2bfloat16(w);
        g_wh[i] = h;
        g_wl[i] = __float2bfloat16(w - __bfloat162float(h));
    }
    if (blockIdx.x == 0 && threadIdx.x < 32) {
        unsigned long long v = ei[threadIdx.x];
        unsigned mask = __ballot_sync(0xffffffffu, (v >> 32) != 0ull);
        if (threadIdx.x == 0) g_is64 = (mask == 0u) ? 1 : 0;
    }
}

__device__ __forceinline__ void edge_rc(const void* ei, int is64, int e, int& r, int& c) {
    if (is64) {
        const long long* p = (const long long*)ei;
        r = (int)p[e];
        c = (int)p[N_EDGES + e];
    } else {
        const int* p = (const int*)ei;
        r = p[e];
        c = p[N_EDGES + e];
    }
}

__global__ void k_hist(const void* __restrict__ ei) {
    int is64 = g_is64;
    for (int e = blockIdx.x * blockDim.x + threadIdx.x; e < N_EDGES;
         e += gridDim.x * blockDim.x) {
        int r, c;
        edge_rc(ei, is64, e, r, c);
        atomicAdd(&g_degI[r], 1);
        atomicAdd(&g_colcnt[c], 1);
    }
}

// ---- 2-stage scan: per-block exclusive + raw totals; prefix folded into stage 2 ----
__global__ void k_scan1() {
    __shared__ int wsum[8];
    const int tid = threadIdx.x, lane = tid & 31, wid = tid >> 5;
    int i = blockIdx.x * 256 + tid;
    int v = (i < N_NODES) ? g_colcnt[i] : 0;
    int x = v;
#pragma unroll
    for (int d = 1; d < 32; d <<= 1) {
        int t = __shfl_up_sync(0xffffffffu, x, d);
        if (lane >= d) x += t;
    }
    if (lane == 31) wsum[wid] = x;
    __syncthreads();
    if (wid == 0 && lane < 8) {
        int y = wsum[lane];
#pragma unroll
        for (int d = 1; d < 8; d <<= 1) {
            int t = __shfl_up_sync(0xffu, y, d);
            if (lane >= d) y += t;
        }
        wsum[lane] = y;
    }
    __syncthreads();
    int excl = x - v + (wid > 0 ? wsum[wid - 1] : 0);
    if (i < N_NODES) g_offsets[i] = excl;
    if (tid == 255) g_blocksum[blockIdx.x] = excl + v;   // raw block total
}

// stage 2: each block computes its prefix over raw blocksums, then finalizes
// offsets/cursor/dinv for its 256-node chunk
__global__ void k_scan3() {
    __shared__ int wred[8];
    const int tid = threadIdx.x, lane = tid & 31, wid = tid >> 5;
    const int chunk = blockIdx.x;

    int v = (tid < chunk) ? g_blocksum[tid] : 0;   // chunk <= 195 < 256
#pragma unroll
    for (int d = 16; d > 0; d >>= 1)
        v += __shfl_down_sync(0xffffffffu, v, d);
    if (lane == 0) wred[wid] = v;
    __syncthreads();
    if (wid == 0) {
        int y = (lane < 8) ? wred[lane] : 0;
#pragma unroll
        for (int d = 4; d > 0; d >>= 1)
            y += __shfl_down_sync(0xffffffffu, y, d);
        if (lane == 0) wred[0] = y;
    }
    __syncthreads();
    const int prefix = wred[0];

    int i = chunk * 256 + tid;
    if (i < N_NODES) {
        int o = g_offsets[i] + prefix;
        g_offsets[i] = o;
        g_cursor[i] = o;
        int dg = g_degI[i];
        g_dinv[i] = (dg > 0) ? rsqrtf((float)dg) : 0.0f;
    }
    if (i == 0) g_offsets[N_NODES] = N_EDGES;
}

__global__ void k_fill(const void* __restrict__ ei) {
    int is64 = g_is64;
    for (int e = blockIdx.x * blockDim.x + threadIdx.x; e < N_EDGES;
         e += gridDim.x * blockDim.x) {
        int r, c;
        edge_rc(ei, is64, e, r, c);
        int p = atomicAdd(&g_cursor[c], 1);
        g_erow[p] = r;
    }
}

// ---------------- tensor GEMM: h = fp16((x@W^T + b)*dinv[row]) ----------------
// bf16 Markidis split: acc = xh*Wh + xh*Wl + xl*Wh (fp32 accum).
// CTA: 128x128 tile, 512 threads / 16 warps, warp tile 32x32.
__global__ void __launch_bounds__(512, 1)
k_gemm(const float* __restrict__ x, int layer, const float* __restrict__ bvec) {
    extern __shared__ char sm[];
    __nv_bfloat16* xh = (__nv_bfloat16*)(sm + OFF_XH);
    __nv_bfloat16* xl = (__nv_bfloat16*)(sm + OFF_XL);
    __nv_bfloat16* wh = (__nv_bfloat16*)(sm + OFF_WH);
    __nv_bfloat16* wl = (__nv_bfloat16*)(sm + OFF_WL);

    const int tid = threadIdx.x, lane = tid & 31, wid = tid >> 5;
    const int row0 = blockIdx.x * 128;

    // copy precomputed W splits (bf16, no math)
    {
        const uint4* gwh = (const uint4*)(g_wh + layer * D * D);
        const uint4* gwl = (const uint4*)(g_wl + layer * D * D);
        for (int t = tid; t < 2048; t += 512) {
            int r = t >> 4, c8 = (t & 15) * 8;
            *(uint4*)&wh[r * TPITCH + c8] = gwh[t];
            *(uint4*)&wl[r * TPITCH + c8] = gwl[t];
        }
    }
    // load + split x tile
    for (int t = tid; t < 4096; t += 512) {
        int r = t >> 5, c = (t & 31) * 4;
        int gr = row0 + r;
        float4 v = (gr < N_NODES) ? *(const float4*)&x[(size_t)gr * D + c]
                                  : make_float4(0.f, 0.f, 0.f, 0.f);
        __nv_bfloat16 h0 = __float2bfloat16(v.x), h1 = __float2bfloat16(v.y);
        __nv_bfloat16 h2 = __float2bfloat16(v.z), h3 = __float2bfloat16(v.w);
        __nv_bfloat162 hp0 = __halves2bfloat162(h0, h1), hp1 = __halves2bfloat162(h2, h3);
        __nv_bfloat162 lp0 = __halves2bfloat162(__float2bfloat16(v.x - __bfloat162float(h0)),
                                                __float2bfloat16(v.y - __bfloat162float(h1)));
        __nv_bfloat162 lp1 = __halves2bfloat162(__float2bfloat16(v.z - __bfloat162float(h2)),
                                                __float2bfloat16(v.w - __bfloat162float(h3)));
        uint2 ph, pl;
        ph.x = *(unsigned*)&hp0; ph.y = *(unsigned*)&hp1;
        pl.x = *(unsigned*)&lp0; pl.y = *(unsigned*)&lp1;
        *(uint2*)&xh[r * TPITCH + c] = ph;
        *(uint2*)&xl[r * TPITCH + c] = pl;
    }
    if (blockIdx.x == 0) {
        if (tid < 2 * D) g_stats[tid] = 0.0f;
        if (tid == 0) g_bnctr = 0;   // reset last-block counter for this layer's gather
    }
    __syncthreads();

    const int wm = wid >> 2;          // 0..3 : rows wm*32 .. +31
    const int wn = wid & 3;           // 0..3 : cols wn*32 .. +31
    const int lrow = lane & 15;
    const int lksh = (lane >> 4) * 8;

    float acc[2][4][4];
#pragma unroll
    for (int mi = 0; mi < 2; mi++)
#pragma unroll
        for (int ni = 0; ni < 4; ni++)
#pragma unroll
            for (int j = 0; j < 4; j++) acc[mi][ni][j] = 0.0f;

    const uint32_t sxh = smem_u32(xh), sxl = smem_u32(xl);
    const uint32_t swh = smem_u32(wh), swl = smem_u32(wl);

#pragma unroll
    for (int pass = 0; pass < 3; pass++) {
        const uint32_t abase = (pass == 2) ? sxl : sxh;
        const uint32_t bbase = (pass == 1) ? swl : swh;
#pragma unroll
        for (int k0 = 0; k0 < 128; k0 += 16) {
            uint32_t af[2][4];
#pragma unroll
            for (int mi = 0; mi < 2; mi++) {
                uint32_t a = abase +
                    (uint32_t)(((wm * 32 + mi * 16 + lrow) * TPITCH + k0 + lksh) * 2);
                ldm_x4(af[mi][0], af[mi][1], af[mi][2], af[mi][3], a);
            }
            uint32_t bf[2][4];
#pragma unroll
            for (int nh = 0; nh < 2; nh++) {
                uint32_t a = bbase +
                    (uint32_t)(((wn * 32 + nh * 16 + lrow) * TPITCH + k0 + lksh) * 2);
                ldm_x4(bf[nh][0], bf[nh][1], bf[nh][2], bf[nh][3], a);
            }
#pragma unroll
            for (int mi = 0; mi < 2; mi++)
#pragma unroll
                for (int ni = 0; ni < 4; ni++) {
                    int nh = ni >> 1, nl = ni & 1;
                    mma_bf16(acc[mi][ni][0], acc[mi][ni][1], acc[mi][ni][2], acc[mi][ni][3],
                             af[mi][0], af[mi][1], af[mi][2], af[mi][3],
                             bf[nh][nl], bf[nh][nl + 2]);
                }
        }
    }

    // epilogue: (acc + bias) * dinv[row] -> fp16 pairs
    const int g = lane >> 2, tg = lane & 3;
    uint32_t* hw = (uint32_t*)g_h;
#pragma unroll
    for (int mi = 0; mi < 2; mi++) {
        int r0g = row0 + wm * 32 + mi * 16 + g;
        int r1g = r0g + 8;
        float dv0 = (r0g < N_NODES) ? g_dinv[r0g] : 0.0f;
        float dv1 = (r1g < N_NODES) ? g_dinv[r1g] : 0.0f;
#pragma unroll
        for (int ni = 0; ni < 4; ni++) {
            int c = wn * 32 + ni * 8 + 2 * tg;
            float b0 = bvec[c], b1 = bvec[c + 1];
            if (r0g < N_NODES) {
                __half2 p = __floats2half2_rn((acc[mi][ni][0] + b0) * dv0,
                                              (acc[mi][ni][1] + b1) * dv0);
                hw[(size_t)r0g * 64 + (c >> 1)] = *(uint32_t*)&p;
            }
            if (r1g < N_NODES) {
                __half2 p = __floats2half2_rn((acc[mi][ni][2] + b0) * dv1,
                                              (acc[mi][ni][3] + b1) * dv1);
                hw[(size_t)r1g * 64 + (c >> 1)] = *(uint32_t*)&p;
            }
        }
    }
}

// ---------------- gather: agg[n] = fp16(dinv[n]*sum h[row_e]); fused BN stats + bnfinal ----------------
// Stats from ROUNDED fp16 values. The LAST block to finish (global counter)
// computes g_bn scale/shift — replaces the separate k_bnfinal launch.
__global__ void k_gather(const float* __restrict__ gamma, const float* __restrict__ beta) {
    const int lane = threadIdx.x & 31;
    const int warp = threadIdx.x >> 5;
    const int gw   = blockIdx.x * 8 + warp;
    const int nw   = gridDim.x * 8;
    const uint2* __restrict__ hp = g_h;
    uint2* ap = g_agg;

    float s0 = 0.f, s1 = 0.f, s2 = 0.f, s3 = 0.f;
    float q0 = 0.f, q1 = 0.f, q2 = 0.f, q3 = 0.f;

    for (int node = gw; node < N_NODES; node += nw) {
        int st = g_offsets[node];
        int en = g_offsets[node + 1];
        float4 acc = make_float4(0.f, 0.f, 0.f, 0.f);
        for (int i = st; i < en; i += 32) {
            int idx = 0;
            if (i + lane < en) idx = g_erow[i + lane];
            int n = min(32, en - i);
#pragma unroll 4
            for (int j = 0; j < n; j++) {
                int r = __shfl_sync(0xffffffffu, idx, j);
                uint2 v = hp[(size_t)r * 32 + lane];
                __half2 a = *reinterpret_cast<__half2*>(&v.x);
                __half2 b = *reinterpret_cast<__half2*>(&v.y);
                float2 f0 = __half22float2(a);
                float2 f1 = __half22float2(b);
                acc.x += f0.x; acc.y += f0.y; acc.z += f1.x; acc.w += f1.y;
            }
        }
        float dc = g_dinv[node];
        __half2 p0 = __floats2half2_rn(acc.x * dc, acc.y * dc);
        __half2 p1 = __floats2half2_rn(acc.z * dc, acc.w * dc);
        uint2 pk;
        pk.x = *(unsigned*)&p0;
        pk.y = *(unsigned*)&p1;
        ap[(size_t)node * 32 + lane] = pk;
        float2 r0 = __half22float2(p0);
        float2 r1 = __half22float2(p1);
        s0 += r0.x; s1 += r0.y; s2 += r1.x; s3 += r1.y;
        q0 += r0.x * r0.x; q1 += r0.y * r0.y;
        q2 += r1.x * r1.x; q3 += r1.y * r1.y;
    }

    __shared__ float ssum[128], ssq[128];
    __shared__ int s_last;
    if (threadIdx.x < 128) { ssum[threadIdx.x] = 0.f; ssq[threadIdx.x] = 0.f; }
    __syncthreads();
    int c = lane * 4;
    atomicAdd(&ssum[c + 0], s0); atomicAdd(&ssum[c + 1], s1);
    atomicAdd(&ssum[c + 2], s2); atomicAdd(&ssum[c + 3], s3);
    atomicAdd(&ssq[c + 0], q0); atomicAdd(&ssq[c + 1], q1);
    atomicAdd(&ssq[c + 2], q2); atomicAdd(&ssq[c + 3], q3);
    __syncthreads();
    if (threadIdx.x < 128) {
        atomicAdd(&g_stats[threadIdx.x], ssum[threadIdx.x]);
        atomicAdd(&g_stats[D + threadIdx.x], ssq[threadIdx.x]);
    }
    // last-block bnfinal
    __threadfence();
    __syncthreads();
    if (threadIdx.x == 0)
        s_last = (atomicAdd(&g_bnctr, 1) == gridDim.x - 1) ? 1 : 0;
    __syncthreads();
    if (s_last && threadIdx.x < 128) {
        int cc = threadIdx.x;
        const float inv_n = 1.0f / (float)N_NODES;
        float mu  = g_stats[cc] * inv_n;
        float var = g_stats[D + cc] * inv_n - mu * mu;
        float sc  = gamma[cc] * rsqrtf(var + BN_EPS);
        g_bn[cc]     = sc;
        g_bn[D + cc] = beta[cc] - mu * sc;
    }
}

__global__ void k_apply(const float* __restrict__ xsrc, float* __restrict__ xdst) {
    int i = blockIdx.x * blockDim.x + threadIdx.x;
    if (i >= N_NODES * 32) return;
    int cq = i & 31;
    uint2 av = g_agg[i];
    __half2 a0 = *reinterpret_cast<__half2*>(&av.x);
    __half2 a1 = *reinterpret_cast<__half2*>(&av.y);
    float2 f0 = __half22float2(a0);
    float2 f1 = __half22float2(a1);
    float4 xv = ((const float4*)xsrc)[i];
    float4 sc = ((const float4*)g_bn)[cq];
    float4 sh = ((const float4*)(g_bn + D))[cq];
    float4 o;
    o.x = xv.x + fmaxf(fmaf(f0.x, sc.x, sh.x), 0.f);
    o.y = xv.y + fmaxf(fmaf(f0.y, sc.y, sh.y), 0.f);
    o.z = xv.z + fmaxf(fmaf(f1.x, sc.z, sh.z), 0.f);
    o.w = xv.w + fmaxf(fmaf(f1.y, sc.w, sh.w), 0.f);
    ((float4*)xdst)[i] = o;
}

// ---------------- launch ----------------
extern "C" void kernel_launch(void* const* d_in, const int* in_sizes, int n_in,
                              void* d_out, int out_size) {
    const float* x     = (const float*)d_in[0];
    const void*  ei    = d_in[1];
    const float* W     = (const float*)d_in[2];
    const float* bvec  = (const float*)d_in[3];
    const float* gamma = (const float*)d_in[4];
    const float* beta  = (const float*)d_in[5];
    float* out = (float*)d_out;

    cudaFuncSetAttribute(k_gemm, cudaFuncAttributeMaxDynamicSharedMemorySize, GEMM_SMEM);

    k_pre<<<160, 256>>>((const unsigned long long*)ei, W);   // 0 (zero + sniff + wsplit)
    k_hist<<<1184, 256>>>(ei);                               // 1
    k_scan1<<<SCAN_NB, 256>>>();                             // 2
    k_scan3<<<SCAN_NB, 256>>>();                             // 3 (prefix folded in)

    const float* xin = x;
    const int gemm_blocks  = (N_NODES + 127) / 128;          // 391
    const int apply_blocks = (N_NODES * 32 + 255) / 256;

    for (int l = 0; l < NL; l++) {
        k_gemm<<<gemm_blocks, 512, GEMM_SMEM>>>(xin, l, bvec + l * D);
        if (l == 0) k_fill<<<1184, 256>>>(ei);
        k_gather<<<GATHER_BLOCKS, 256>>>(gamma + l * D, beta + l * D);
        k_apply<<<apply_blocks, 256>>>(xin, out);
        xin = out;
    }
}